// round 1
// baseline (speedup 1.0000x reference)
#include <cuda_runtime.h>

typedef unsigned long long u64;

#define NB 2
#define NL 2048
#define NDM 1024
#define NH 16
#define NDK 64
#define NBH (NB * NH)   // 32
#define NM (NB * NL)    // 4096

// ---------------- device scratch (alloc-free) ----------------
__device__ float g_Qp[NBH * NL * NDK];          // 16 MB  [B,H,L,DK]
__device__ float g_Kp[NBH * NL * NDK];          // 16 MB
__device__ float g_Vp[NBH * NL * NDK];          // 16 MB
__device__ float g_S[(size_t)NBH * NL * NL];    // 512 MB [B,H,Lq,Lk]
__device__ float g_Zr[NBH * NL];                // 1/Z per (b,h,s)
__device__ float g_O[(size_t)NM * NDM];         // 16 MB  cat_V [B*L, H*DV]

// ---------------- packed f32x2 helpers ----------------
__device__ __forceinline__ u64 pk2(float lo, float hi) {
    u64 r;
    asm("mov.b64 %0, {%1, %2};" : "=l"(r) : "f"(lo), "f"(hi));
    return r;
}
__device__ __forceinline__ void fma2(u64 &d, u64 a, u64 b) {
    asm("fma.rn.f32x2 %0, %1, %2, %0;" : "+l"(d) : "l"(a), "l"(b));
}
__device__ __forceinline__ float2 upk2(u64 v) {
    float lo, hi;
    asm("mov.b64 {%0, %1}, %2;" : "=f"(lo), "=f"(hi) : "l"(v));
    return make_float2(lo, hi);
}

// all-FFMA exp (no MUFU): exp(x) = 2^(x*log2e), magic-number round,
// degree-5 Taylor of 2^f on [-0.5,0.5] (rel err ~3e-6)
__device__ __forceinline__ float fast_exp(float x) {
    float t = x * 1.4426950408889634f;
    t = fmaxf(t, -126.0f);
    float r = t + 12582912.0f;             // 1.5*2^23: mantissa holds round(t)
    int   i = __float_as_int(r);           // low bits = biased integer part
    float rf = r - 12582912.0f;
    float f = t - rf;                      // f in [-0.5, 0.5]
    float p = 1.33335581e-3f;
    p = fmaf(p, f, 9.61812911e-3f);
    p = fmaf(p, f, 5.55041087e-2f);
    p = fmaf(p, f, 2.40226507e-1f);
    p = fmaf(p, f, 6.93147180e-1f);
    p = fmaf(p, f, 1.0f);
    return __int_as_float(__float_as_int(p) + (i << 23));
}

// ---------------- shared microkernel ----------------
// Tile: 128(M) x 64(N) x 16(K), 256 threads, 8x4 per thread.
// As[k][m] (transposed), Bs[k][n] pre-duplicated {b,b} u64.
// acc[p][j] = packed {C[m0+2p][n], C[m0+2p+1][n]}, m0=ty*8, n=tx*4+j.
__device__ __forceinline__ void mk_inner(const float (*As)[128], const u64 (*Bs)[64],
                                         int tx, int ty, u64 acc[4][4]) {
#pragma unroll
    for (int kk = 0; kk < 16; ++kk) {
        ulonglong2 a01 = *(const ulonglong2 *)&As[kk][ty * 8];
        ulonglong2 a23 = *(const ulonglong2 *)&As[kk][ty * 8 + 4];
        ulonglong2 b01 = *(const ulonglong2 *)&Bs[kk][tx * 4];
        ulonglong2 b23 = *(const ulonglong2 *)&Bs[kk][tx * 4 + 2];
        u64 ap[4] = {a01.x, a01.y, a23.x, a23.y};
        u64 bp[4] = {b01.x, b01.y, b23.x, b23.y};
#pragma unroll
        for (int p = 0; p < 4; ++p)
#pragma unroll
            for (int j = 0; j < 4; ++j) fma2(acc[p][j], ap[p], bp[j]);
    }
}

#define ACC_INIT(acc)                                   \
    do {                                                \
        _Pragma("unroll") for (int p = 0; p < 4; ++p)   \
            _Pragma("unroll") for (int j = 0; j < 4; ++j) acc[p][j] = 0ULL; \
    } while (0)

// ---------------- kernel 1: per-head input projections ----------------
// X [B*L, DM] @ Wh [DM, DK] + bias -> out [B,H,L,DK]; BN=64=DK so blockIdx.y = head
__global__ void __launch_bounds__(256) proj_kernel(const float *__restrict__ X,
                                                   const float *__restrict__ W,
                                                   const float *__restrict__ bias,
                                                   int which) {
    __shared__ float As[16][128];
    __shared__ u64   Bs[16][64];
    float *out = (which == 0) ? g_Qp : (which == 1) ? g_Kp : g_Vp;
    const int tid = threadIdx.x;
    const int tx = tid & 15, ty = tid >> 4;
    const int row0 = blockIdx.x * 128;
    const int h = blockIdx.y;
    const float *Wh = W + (size_t)h * NDM * NDK;
    const int arow = tid >> 1, ak = (tid & 1) * 8;
    const int bk = tid >> 4, bn = (tid & 15) * 4;

    u64 acc[4][4];
    ACC_INIT(acc);

    for (int k0 = 0; k0 < NDM; k0 += 16) {
        float4 a0 = *(const float4 *)(X + (size_t)(row0 + arow) * NDM + k0 + ak);
        float4 a1 = *(const float4 *)(X + (size_t)(row0 + arow) * NDM + k0 + ak + 4);
        As[ak + 0][arow] = a0.x; As[ak + 1][arow] = a0.y;
        As[ak + 2][arow] = a0.z; As[ak + 3][arow] = a0.w;
        As[ak + 4][arow] = a1.x; As[ak + 5][arow] = a1.y;
        As[ak + 6][arow] = a1.z; As[ak + 7][arow] = a1.w;
        float4 bv = *(const float4 *)(Wh + (size_t)(k0 + bk) * NDK + bn);
        Bs[bk][bn + 0] = pk2(bv.x, bv.x);
        Bs[bk][bn + 1] = pk2(bv.y, bv.y);
        Bs[bk][bn + 2] = pk2(bv.z, bv.z);
        Bs[bk][bn + 3] = pk2(bv.w, bv.w);
        __syncthreads();
        mk_inner(As, Bs, tx, ty, acc);
        __syncthreads();
    }

    const float4 bia = *(const float4 *)(bias + h * NDK + tx * 4);
#pragma unroll
    for (int p = 0; p < 4; ++p) {
        float2 c0 = upk2(acc[p][0]), c1 = upk2(acc[p][1]);
        float2 c2 = upk2(acc[p][2]), c3 = upk2(acc[p][3]);
        int row = row0 + ty * 8 + 2 * p;
        int b = row >> 11, l = row & (NL - 1);
        float *o = out + ((size_t)(b * NH + h) * NL + l) * NDK + tx * 4;
        *(float4 *)o = make_float4(c0.x + bia.x, c1.x + bia.y, c2.x + bia.z, c3.x + bia.w);
        o += NDK;  // l+1 (tiles never straddle batch: 2048 % 128 == 0)
        *(float4 *)o = make_float4(c0.y + bia.x, c1.y + bia.y, c2.y + bia.z, c3.y + bia.w);
    }
}

// ---------------- kernel 2: scores S = Qp @ Kp^T / sqrt(DK) ----------------
__global__ void __launch_bounds__(256) scores_kernel() {
    __shared__ float As[16][128];
    __shared__ u64   Bs[16][64];
    const int tid = threadIdx.x;
    const int tx = tid & 15, ty = tid >> 4;
    const int q0 = blockIdx.x * 128;
    const int s0 = blockIdx.y * 64;
    const int bh = blockIdx.z;
    const float *Qb = g_Qp + (size_t)bh * NL * NDK;
    const float *Kb = g_Kp + (size_t)bh * NL * NDK;
    const int arow = tid >> 1, ak = (tid & 1) * 8;
    const int brow = tid & 63, bks = (tid >> 6) * 4;

    u64 acc[4][4];
    ACC_INIT(acc);

    for (int k0 = 0; k0 < NDK; k0 += 16) {
        float4 a0 = *(const float4 *)(Qb + (size_t)(q0 + arow) * NDK + k0 + ak);
        float4 a1 = *(const float4 *)(Qb + (size_t)(q0 + arow) * NDK + k0 + ak + 4);
        As[ak + 0][arow] = a0.x; As[ak + 1][arow] = a0.y;
        As[ak + 2][arow] = a0.z; As[ak + 3][arow] = a0.w;
        As[ak + 4][arow] = a1.x; As[ak + 5][arow] = a1.y;
        As[ak + 6][arow] = a1.z; As[ak + 7][arow] = a1.w;
        float4 bv = *(const float4 *)(Kb + (size_t)(s0 + brow) * NDK + k0 + bks);
        Bs[bks + 0][brow] = pk2(bv.x, bv.x);
        Bs[bks + 1][brow] = pk2(bv.y, bv.y);
        Bs[bks + 2][brow] = pk2(bv.z, bv.z);
        Bs[bks + 3][brow] = pk2(bv.w, bv.w);
        __syncthreads();
        mk_inner(As, Bs, tx, ty, acc);
        __syncthreads();
    }

    float *Sb = g_S + (size_t)bh * NL * NL;
    const float sc = 0.125f;  // 1/sqrt(64)
#pragma unroll
    for (int p = 0; p < 4; ++p) {
        float2 c0 = upk2(acc[p][0]), c1 = upk2(acc[p][1]);
        float2 c2 = upk2(acc[p][2]), c3 = upk2(acc[p][3]);
        int q = q0 + ty * 8 + 2 * p;
        *(float4 *)(Sb + (size_t)q * NL + s0 + tx * 4) =
            make_float4(c0.x * sc, c1.x * sc, c2.x * sc, c3.x * sc);
        *(float4 *)(Sb + (size_t)(q + 1) * NL + s0 + tx * 4) =
            make_float4(c0.y * sc, c1.y * sc, c2.y * sc, c3.y * sc);
    }
}

// ---------------- kernel 3: column softmax stats (over q axis!) ----------------
// Replaces S with exp(S - colmax) in place, stores 1/colsum.
__global__ void __launch_bounds__(256) softmax_cols() {
    const int bh = blockIdx.y;
    const int s = blockIdx.x * 256 + threadIdx.x;
    float *col = g_S + (size_t)bh * NL * NL + s;
    float m = -1e30f;
#pragma unroll 8
    for (int q = 0; q < NL; ++q) m = fmaxf(m, col[(size_t)q * NL]);
    float z = 0.0f;
#pragma unroll 4
    for (int q = 0; q < NL; ++q) {
        float e = fast_exp(col[(size_t)q * NL] - m);
        col[(size_t)q * NL] = e;
        z += e;
    }
    g_Zr[bh * NL + s] = 1.0f / z;
}

// ---------------- kernel 4: O = P @ Vp (P = exp'd S scaled by 1/Z[s]) ----------------
// Writes directly into cat_V layout [B*L, H*DV].
__global__ void __launch_bounds__(256) pv_kernel() {
    __shared__ float As[16][128];
    __shared__ u64   Bs[16][64];
    const int tid = threadIdx.x;
    const int tx = tid & 15, ty = tid >> 4;
    const int q0 = blockIdx.x * 128;
    const int bh = blockIdx.y;
    const int b = bh >> 4, h = bh & 15;
    const float *Sb = g_S + (size_t)bh * NL * NL;
    const float *Vb = g_Vp + (size_t)bh * NL * NDK;
    const float *Zr = g_Zr + bh * NL;
    const int arow = tid >> 1, ak = (tid & 1) * 8;
    const int bk = tid >> 4, bn = (tid & 15) * 4;

    u64 acc[4][4];
    ACC_INIT(acc);

    for (int k0 = 0; k0 < NL; k0 += 16) {
        float4 a0 = *(const float4 *)(Sb + (size_t)(q0 + arow) * NL + k0 + ak);
        float4 a1 = *(const float4 *)(Sb + (size_t)(q0 + arow) * NL + k0 + ak + 4);
        float4 z0 = *(const float4 *)(Zr + k0 + ak);
        float4 z1 = *(const float4 *)(Zr + k0 + ak + 4);
        As[ak + 0][arow] = a0.x * z0.x; As[ak + 1][arow] = a0.y * z0.y;
        As[ak + 2][arow] = a0.z * z0.z; As[ak + 3][arow] = a0.w * z0.w;
        As[ak + 4][arow] = a1.x * z1.x; As[ak + 5][arow] = a1.y * z1.y;
        As[ak + 6][arow] = a1.z * z1.z; As[ak + 7][arow] = a1.w * z1.w;
        float4 bv = *(const float4 *)(Vb + (size_t)(k0 + bk) * NDK + bn);
        Bs[bk][bn + 0] = pk2(bv.x, bv.x);
        Bs[bk][bn + 1] = pk2(bv.y, bv.y);
        Bs[bk][bn + 2] = pk2(bv.z, bv.z);
        Bs[bk][bn + 3] = pk2(bv.w, bv.w);
        __syncthreads();
        mk_inner(As, Bs, tx, ty, acc);
        __syncthreads();
    }

    float *Ob = g_O + (size_t)b * NL * NDM + (size_t)h * NDK;
#pragma unroll
    for (int p = 0; p < 4; ++p) {
        float2 c0 = upk2(acc[p][0]), c1 = upk2(acc[p][1]);
        float2 c2 = upk2(acc[p][2]), c3 = upk2(acc[p][3]);
        int q = q0 + ty * 8 + 2 * p;
        *(float4 *)(Ob + (size_t)q * NDM + tx * 4) = make_float4(c0.x, c1.x, c2.x, c3.x);
        *(float4 *)(Ob + (size_t)(q + 1) * NDM + tx * 4) = make_float4(c0.y, c1.y, c2.y, c3.y);
    }
}

// ---------------- kernel 5: out = cat_V @ Wo + bo ----------------
__global__ void __launch_bounds__(256) out_kernel(const float *__restrict__ Wo,
                                                  const float *__restrict__ bo,
                                                  float *__restrict__ out) {
    __shared__ float As[16][128];
    __shared__ u64   Bs[16][64];
    const int tid = threadIdx.x;
    const int tx = tid & 15, ty = tid >> 4;
    const int row0 = blockIdx.x * 128;
    const int n0 = blockIdx.y * 64;
    const int arow = tid >> 1, ak = (tid & 1) * 8;
    const int bk = tid >> 4, bn = (tid & 15) * 4;

    u64 acc[4][4];
    ACC_INIT(acc);

    for (int k0 = 0; k0 < NDM; k0 += 16) {
        float4 a0 = *(const float4 *)(g_O + (size_t)(row0 + arow) * NDM + k0 + ak);
        float4 a1 = *(const float4 *)(g_O + (size_t)(row0 + arow) * NDM + k0 + ak + 4);
        As[ak + 0][arow] = a0.x; As[ak + 1][arow] = a0.y;
        As[ak + 2][arow] = a0.z; As[ak + 3][arow] = a0.w;
        As[ak + 4][arow] = a1.x; As[ak + 5][arow] = a1.y;
        As[ak + 6][arow] = a1.z; As[ak + 7][arow] = a1.w;
        float4 bv = *(const float4 *)(Wo + (size_t)(k0 + bk) * NDM + n0 + bn);
        Bs[bk][bn + 0] = pk2(bv.x, bv.x);
        Bs[bk][bn + 1] = pk2(bv.y, bv.y);
        Bs[bk][bn + 2] = pk2(bv.z, bv.z);
        Bs[bk][bn + 3] = pk2(bv.w, bv.w);
        __syncthreads();
        mk_inner(As, Bs, tx, ty, acc);
        __syncthreads();
    }

    const float4 bia = *(const float4 *)(bo + n0 + tx * 4);
#pragma unroll
    for (int p = 0; p < 4; ++p) {
        float2 c0 = upk2(acc[p][0]), c1 = upk2(acc[p][1]);
        float2 c2 = upk2(acc[p][2]), c3 = upk2(acc[p][3]);
        int row = row0 + ty * 8 + 2 * p;
        *(float4 *)(out + (size_t)row * NDM + n0 + tx * 4) =
            make_float4(c0.x + bia.x, c1.x + bia.y, c2.x + bia.z, c3.x + bia.w);
        *(float4 *)(out + (size_t)(row + 1) * NDM + n0 + tx * 4) =
            make_float4(c0.y + bia.x, c1.y + bia.y, c2.y + bia.z, c3.y + bia.w);
    }
}

// ---------------- launch ----------------
extern "C" void kernel_launch(void* const* d_in, const int* in_sizes, int n_in,
                              void* d_out, int out_size) {
    const float *Q  = (const float *)d_in[0];
    const float *K  = (const float *)d_in[1];
    const float *V  = (const float *)d_in[2];
    const float *Wq = (const float *)d_in[3];
    const float *bq = (const float *)d_in[4];
    const float *Wk = (const float *)d_in[5];
    const float *bk = (const float *)d_in[6];
    const float *Wv = (const float *)d_in[7];
    const float *bv = (const float *)d_in[8];
    const float *Wo = (const float *)d_in[9];
    const float *bo = (const float *)d_in[10];
    float *out = (float *)d_out;

    proj_kernel<<<dim3(NM / 128, NH), 256>>>(Q, Wq, bq, 0);
    proj_kernel<<<dim3(NM / 128, NH), 256>>>(K, Wk, bk, 1);
    proj_kernel<<<dim3(NM / 128, NH), 256>>>(V, Wv, bv, 2);
    scores_kernel<<<dim3(NL / 128, NL / 64, NBH), 256>>>();
    softmax_cols<<<dim3(NL / 256, NBH), 256>>>();
    pv_kernel<<<dim3(NL / 128, NBH), 256>>>();
    out_kernel<<<dim3(NM / 128, NDM / 64), 256>>>(Wo, bo, out);
}

// round 3
// speedup vs baseline: 2.7344x; 2.7344x over previous
#include <cuda_runtime.h>
#include <cuda_bf16.h>
#include <cstdint>

#define NB 2
#define NL 2048
#define NDM 1024
#define NH 16
#define NDK 64
#define NBH 32
#define NM 4096

// ---------------- device scratch (alloc-free) ----------------
__device__ float g_Qp[NBH * NL * NDK];                 // [B,H,L,DK]
__device__ float g_Kp[NBH * NL * NDK];
__device__ float g_Vp[NBH * NL * NDK];
__device__ __nv_bfloat16 g_Ehi[(size_t)NBH * NL * NL]; // exp(scores) hi
__device__ __nv_bfloat16 g_Elo[(size_t)NBH * NL * NL]; // exp(scores) lo
__device__ float g_Zr[NBH * NL];                       // 1/colsum
__device__ float g_O[(size_t)NM * NDM];                // cat_V

// smem: A tiles 128x64 bf16 (16KB each), B tiles 64x64 bf16 (8KB each)
#define OFF_AHI 0
#define OFF_ALO 16384
#define OFF_BHI 32768
#define OFF_BLO 40960
#define SMEM_BYTES 49152

__device__ __forceinline__ uint32_t s2u(const void *p) {
    uint32_t a;
    asm("{ .reg .u64 t; cvta.to.shared.u64 t, %1; cvt.u32.u64 %0, t; }" : "=r"(a) : "l"(p));
    return a;
}
__device__ __forceinline__ uint32_t swz(uint32_t o) { return o ^ ((o >> 3) & 0x70); }

__device__ __forceinline__ void ldsm4(uint32_t r[4], uint32_t addr) {
    asm volatile("ldmatrix.sync.aligned.m8n8.x4.shared.b16 {%0,%1,%2,%3}, [%4];"
                 : "=r"(r[0]), "=r"(r[1]), "=r"(r[2]), "=r"(r[3]) : "r"(addr));
}
__device__ __forceinline__ void mma16816(float d[4], const uint32_t a[4], const uint32_t b0, const uint32_t b1) {
    asm volatile("mma.sync.aligned.m16n8k16.row.col.f32.bf16.bf16.f32 "
                 "{%0,%1,%2,%3}, {%4,%5,%6,%7}, {%8,%9}, {%0,%1,%2,%3};"
                 : "+f"(d[0]), "+f"(d[1]), "+f"(d[2]), "+f"(d[3])
                 : "r"(a[0]), "r"(a[1]), "r"(a[2]), "r"(a[3]), "r"(b0), "r"(b1));
}

// ---------------- math ----------------
__device__ __forceinline__ float fast_exp(float x) {
    float t = x * 1.4426950408889634f;
    t = fmaxf(t, -126.0f);
    float r = t + 12582912.0f;
    int i = __float_as_int(r);
    float f = t - (r - 12582912.0f);
    float p = 1.33335581e-3f;
    p = fmaf(p, f, 9.61812911e-3f);
    p = fmaf(p, f, 5.55041087e-2f);
    p = fmaf(p, f, 2.40226507e-1f);
    p = fmaf(p, f, 6.93147180e-1f);
    p = fmaf(p, f, 1.0f);
    return __int_as_float(__float_as_int(p) + (i << 23));
}

// ---------------- SMEM tile loaders (split fp32 -> bf16 hi/lo) ----------------
__device__ __forceinline__ void split8_sts(uint32_t dhi, uint32_t dlo, const float f[8]) {
    uint32_t h[4], l[4];
#pragma unroll
    for (int i = 0; i < 4; ++i) {
        __nv_bfloat162 hb = __floats2bfloat162_rn(f[2 * i], f[2 * i + 1]);
        float2 hf = __bfloat1622float2(hb);
        __nv_bfloat162 lb = __floats2bfloat162_rn(f[2 * i] - hf.x, f[2 * i + 1] - hf.y);
        h[i] = *(uint32_t *)&hb;
        l[i] = *(uint32_t *)&lb;
    }
    asm volatile("st.shared.v4.b32 [%0], {%1,%2,%3,%4};" ::"r"(dhi), "r"(h[0]), "r"(h[1]), "r"(h[2]), "r"(h[3]));
    asm volatile("st.shared.v4.b32 [%0], {%1,%2,%3,%4};" ::"r"(dlo), "r"(l[0]), "r"(l[1]), "r"(l[2]), "r"(l[3]));
}

template <int R>
__device__ __forceinline__ void load_split_rows(uint32_t sb_hi, uint32_t sb_lo,
                                                const float *__restrict__ src, int ldm, int tid) {
    for (int s = tid; s < R * 8; s += 256) {
        int r = s >> 3, c8 = (s & 7) << 3;
        const float4 *p = (const float4 *)(src + (size_t)r * ldm + c8);
        float4 f0 = p[0], f1 = p[1];
        float f[8] = {f0.x, f0.y, f0.z, f0.w, f1.x, f1.y, f1.z, f1.w};
        uint32_t off = swz((uint32_t)(r * 128 + c8 * 2));
        split8_sts(sb_hi + off, sb_lo + off, f);
    }
}

// B[n][k] 64x64 from src[k][n] (stride ldn floats), optional per-k scale
template <bool SCALE>
__device__ __forceinline__ void load_split_trans(uint32_t sb_hi, uint32_t sb_lo,
                                                 const float *__restrict__ src, int ldn,
                                                 const float *__restrict__ zs, int tid) {
    for (int s = tid; s < 512; s += 256) {
        int k8 = (s >> 6) << 3, n = s & 63;
        float f[8];
#pragma unroll
        for (int i = 0; i < 8; ++i) {
            float v = src[(size_t)(k8 + i) * ldn + n];
            if (SCALE) v *= zs[k8 + i];
            f[i] = v;
        }
        uint32_t off = swz((uint32_t)(n * 128 + k8 * 2));
        split8_sts(sb_hi + off, sb_lo + off, f);
    }
}

__device__ __forceinline__ void load_bf16_tile(uint32_t sb, const __nv_bfloat16 *__restrict__ src,
                                               int ldm, int tid) {
    for (int s = tid; s < 1024; s += 256) {
        int r = s >> 3, c8 = (s & 7) << 3;
        uint4 v = *(const uint4 *)(src + (size_t)r * ldm + c8);
        uint32_t off = swz((uint32_t)(r * 128 + c8 * 2));
        asm volatile("st.shared.v4.b32 [%0], {%1,%2,%3,%4};" ::"r"(sb + off), "r"(v.x), "r"(v.y), "r"(v.z), "r"(v.w));
    }
}

// ---------------- HMMA microkernel: 128x64x64, 8 warps (4x2), warp tile 32x32 ----------------
// 3 passes fused per k-chunk: Ahi*Bhi + Ahi*Blo + Alo*Bhi
__device__ __forceinline__ void mma_tile(uint32_t sb, int lane, int wm, int wn, float acc[2][4][4]) {
    const uint32_t xr = (uint32_t)(lane & 7) << 4;
    const int g = lane >> 3;
    const int arow = ((g & 1) << 3) + (lane & 7);
    const uint32_t akh = (uint32_t)((g & 2) << 3);  // 0 or 16 bytes (k-half)
    const uint32_t aA = (uint32_t)(wm * 32 + arow) * 128;
    const uint32_t aAhi = sb + OFF_AHI + aA, aAlo = sb + OFF_ALO + aA;
    const uint32_t aB = (uint32_t)(wn * 32 + g * 8 + (lane & 7)) * 128;
    const uint32_t aBhi = sb + OFF_BHI + aB, aBlo = sb + OFF_BLO + aB;
#pragma unroll
    for (int kk = 0; kk < 4; ++kk) {
        const uint32_t ka = ((uint32_t)(kk * 32) + akh) ^ xr;
        const uint32_t kb0 = ((uint32_t)(kk * 32)) ^ xr;
        const uint32_t kb1 = ((uint32_t)(kk * 32 + 16)) ^ xr;
        uint32_t ah0[4], ah1[4], al0[4], al1[4];
        ldsm4(ah0, aAhi + ka);
        ldsm4(ah1, aAhi + 2048 + ka);
        ldsm4(al0, aAlo + ka);
        ldsm4(al1, aAlo + 2048 + ka);
        uint32_t bh0[4], bh1[4], bl0[4], bl1[4];
        ldsm4(bh0, aBhi + kb0);
        ldsm4(bh1, aBhi + kb1);
        ldsm4(bl0, aBlo + kb0);
        ldsm4(bl1, aBlo + kb1);
#pragma unroll
        for (int nt = 0; nt < 4; ++nt) {
            mma16816(acc[0][nt], ah0, bh0[nt], bh1[nt]);
            mma16816(acc[1][nt], ah1, bh0[nt], bh1[nt]);
            mma16816(acc[0][nt], ah0, bl0[nt], bl1[nt]);
            mma16816(acc[1][nt], ah1, bl0[nt], bl1[nt]);
            mma16816(acc[0][nt], al0, bh0[nt], bh1[nt]);
            mma16816(acc[1][nt], al1, bh0[nt], bh1[nt]);
        }
    }
}

#define ACC_ZERO(acc)                                                     \
    do {                                                                  \
        _Pragma("unroll") for (int _m = 0; _m < 2; ++_m)                  \
            _Pragma("unroll") for (int _n = 0; _n < 4; ++_n)              \
                _Pragma("unroll") for (int _i = 0; _i < 4; ++_i) acc[_m][_n][_i] = 0.f; \
    } while (0)

// ---------------- kernel 1: per-head projections (Q,K,V via blockIdx.z) ----------------
__global__ void __launch_bounds__(256) proj_mm(const float *__restrict__ Q, const float *__restrict__ K,
                                               const float *__restrict__ V,
                                               const float *__restrict__ Wq, const float *__restrict__ bq,
                                               const float *__restrict__ Wk, const float *__restrict__ bk,
                                               const float *__restrict__ Wv, const float *__restrict__ bv) {
    __shared__ char smem[SMEM_BYTES];
    uint32_t sb = s2u(smem);
    const int tid = threadIdx.x, lane = tid & 31, wid = tid >> 5;
    const int wm = wid >> 1, wn = wid & 1;
    const int row0 = blockIdx.x * 128;
    const int h = blockIdx.y;
    const int wz = blockIdx.z;
    const float *X = (wz == 0) ? Q : (wz == 1) ? K : V;
    const float *W = (wz == 0) ? Wq : (wz == 1) ? Wk : Wv;
    const float *bias = (wz == 0) ? bq : (wz == 1) ? bk : bv;
    float *outp = (wz == 0) ? g_Qp : (wz == 1) ? g_Kp : g_Vp;
    const float *Wh = W + (size_t)h * NDM * NDK;

    float acc[2][4][4];
    ACC_ZERO(acc);
    for (int it = 0; it < 16; ++it) {
        __syncthreads();
        load_split_rows<128>(sb + OFF_AHI, sb + OFF_ALO, X + (size_t)row0 * NDM + it * 64, NDM, tid);
        load_split_trans<false>(sb + OFF_BHI, sb + OFF_BLO, Wh + (size_t)(it * 64) * NDK, NDK, nullptr, tid);
        __syncthreads();
        mma_tile(sb, lane, wm, wn, acc);
    }
    const int trow = lane >> 2, tc = (lane & 3) * 2;
#pragma unroll
    for (int mt = 0; mt < 2; ++mt)
#pragma unroll
        for (int nt = 0; nt < 4; ++nt) {
            int col = wn * 32 + nt * 8 + tc;
            float2 b2 = *(const float2 *)(bias + h * NDK + col);
#pragma unroll
            for (int hh = 0; hh < 2; ++hh) {
                int grow = row0 + wm * 32 + mt * 16 + trow + hh * 8;
                int bb = grow >> 11, l = grow & (NL - 1);
                float *o = outp + ((size_t)(bb * NH + h) * NL + l) * NDK + col;
                *(float2 *)o = make_float2(acc[mt][nt][2 * hh] + b2.x, acc[mt][nt][2 * hh + 1] + b2.y);
            }
        }
}

// ---------------- kernel 2: scores + exp + bf16 split store ----------------
__global__ void __launch_bounds__(256) scores_mm() {
    __shared__ char smem[SMEM_BYTES];
    uint32_t sb = s2u(smem);
    const int tid = threadIdx.x, lane = tid & 31, wid = tid >> 5;
    const int wm = wid >> 1, wn = wid & 1;
    const int q0 = blockIdx.x * 128;
    const int s0 = blockIdx.y * 64;
    const int bh = blockIdx.z;
    const float *Qb = g_Qp + (size_t)bh * NL * NDK;
    const float *Kb = g_Kp + (size_t)bh * NL * NDK;

    load_split_rows<128>(sb + OFF_AHI, sb + OFF_ALO, Qb + (size_t)q0 * NDK, NDK, tid);
    load_split_rows<64>(sb + OFF_BHI, sb + OFF_BLO, Kb + (size_t)s0 * NDK, NDK, tid);
    __syncthreads();
    float acc[2][4][4];
    ACC_ZERO(acc);
    mma_tile(sb, lane, wm, wn, acc);

    const int trow = lane >> 2, tc = (lane & 3) * 2;
    const size_t bhbase = (size_t)bh * NL * NL;
#pragma unroll
    for (int mt = 0; mt < 2; ++mt)
#pragma unroll
        for (int nt = 0; nt < 4; ++nt) {
            int col = s0 + wn * 32 + nt * 8 + tc;
#pragma unroll
            for (int hh = 0; hh < 2; ++hh) {
                int q = q0 + wm * 32 + mt * 16 + trow + hh * 8;
                float e0 = fast_exp(acc[mt][nt][2 * hh] * 0.125f);
                float e1 = fast_exp(acc[mt][nt][2 * hh + 1] * 0.125f);
                __nv_bfloat162 hb = __floats2bfloat162_rn(e0, e1);
                float2 hf = __bfloat1622float2(hb);
                __nv_bfloat162 lb = __floats2bfloat162_rn(e0 - hf.x, e1 - hf.y);
                size_t off = bhbase + (size_t)q * NL + col;
                *(uint32_t *)(g_Ehi + off) = *(uint32_t *)&hb;
                *(uint32_t *)(g_Elo + off) = *(uint32_t *)&lb;
            }
        }
}

// ---------------- kernel 3: column sums -> 1/Z ----------------
__global__ void __launch_bounds__(256) colsum_mm() {
    const int bh = blockIdx.y;
    const int cp = blockIdx.x * 256 + threadIdx.x;  // column pair
    const __nv_bfloat162 *ph = (const __nv_bfloat162 *)(g_Ehi + (size_t)bh * NL * NL) + cp;
    const __nv_bfloat162 *pl = (const __nv_bfloat162 *)(g_Elo + (size_t)bh * NL * NL) + cp;
    float z0 = 0.f, z1 = 0.f;
#pragma unroll 8
    for (int q = 0; q < NL; ++q) {
        float2 h = __bfloat1622float2(ph[(size_t)q * (NL / 2)]);
        float2 l = __bfloat1622float2(pl[(size_t)q * (NL / 2)]);
        z0 += h.x + l.x;
        z1 += h.y + l.y;
    }
    g_Zr[bh * NL + 2 * cp] = 1.0f / z0;
    g_Zr[bh * NL + 2 * cp + 1] = 1.0f / z1;
}

// ---------------- kernel 4: O = P @ (Zr*V) ----------------
__global__ void __launch_bounds__(256) pv_mm() {
    __shared__ char smem[SMEM_BYTES];
    uint32_t sb = s2u(smem);
    const int tid = threadIdx.x, lane = tid & 31, wid = tid >> 5;
    const int wm = wid >> 1, wn = wid & 1;
    const int q0 = blockIdx.x * 128;
    const int bh = blockIdx.y;
    const int bb = bh >> 4, h = bh & 15;
    const __nv_bfloat16 *Phi = g_Ehi + (size_t)bh * NL * NL + (size_t)q0 * NL;
    const __nv_bfloat16 *Plo = g_Elo + (size_t)bh * NL * NL + (size_t)q0 * NL;
    const float *Vb = g_Vp + (size_t)bh * NL * NDK;
    const float *Zr = g_Zr + bh * NL;

    float acc[2][4][4];
    ACC_ZERO(acc);
    for (int it = 0; it < 32; ++it) {
        int k0 = it * 64;
        __syncthreads();
        load_bf16_tile(sb + OFF_AHI, Phi + k0, NL, tid);
        load_bf16_tile(sb + OFF_ALO, Plo + k0, NL, tid);
        load_split_trans<true>(sb + OFF_BHI, sb + OFF_BLO, Vb + (size_t)k0 * NDK, NDK, Zr + k0, tid);
        __syncthreads();
        mma_tile(sb, lane, wm, wn, acc);
    }
    const int trow = lane >> 2, tc = (lane & 3) * 2;
#pragma unroll
    for (int mt = 0; mt < 2; ++mt)
#pragma unroll
        for (int nt = 0; nt < 4; ++nt) {
            int col = wn * 32 + nt * 8 + tc;
#pragma unroll
            for (int hh = 0; hh < 2; ++hh) {
                int q = q0 + wm * 32 + mt * 16 + trow + hh * 8;
                float *o = g_O + ((size_t)bb * NL + q) * NDM + (size_t)h * NDK + col;
                *(float2 *)o = make_float2(acc[mt][nt][2 * hh], acc[mt][nt][2 * hh + 1]);
            }
        }
}

// ---------------- kernel 5: out = cat_V @ Wo + bo ----------------
__global__ void __launch_bounds__(256) out_mm(const float *__restrict__ Wo,
                                              const float *__restrict__ bo,
                                              float *__restrict__ out) {
    __shared__ char smem[SMEM_BYTES];
    uint32_t sb = s2u(smem);
    const int tid = threadIdx.x, lane = tid & 31, wid = tid >> 5;
    const int wm = wid >> 1, wn = wid & 1;
    const int row0 = blockIdx.x * 128;
    const int n0 = blockIdx.y * 64;

    float acc[2][4][4];
    ACC_ZERO(acc);
    for (int it = 0; it < 16; ++it) {
        __syncthreads();
        load_split_rows<128>(sb + OFF_AHI, sb + OFF_ALO, g_O + (size_t)row0 * NDM + it * 64, NDM, tid);
        load_split_trans<false>(sb + OFF_BHI, sb + OFF_BLO, Wo + (size_t)(it * 64) * NDM + n0, NDM, nullptr, tid);
        __syncthreads();
        mma_tile(sb, lane, wm, wn, acc);
    }
    const int trow = lane >> 2, tc = (lane & 3) * 2;
#pragma unroll
    for (int mt = 0; mt < 2; ++mt)
#pragma unroll
        for (int nt = 0; nt < 4; ++nt) {
            int col = n0 + wn * 32 + nt * 8 + tc;
            float2 b2 = *(const float2 *)(bo + col);
#pragma unroll
            for (int hh = 0; hh < 2; ++hh) {
                int row = row0 + wm * 32 + mt * 16 + trow + hh * 8;
                *(float2 *)(out + (size_t)row * NDM + col) =
                    make_float2(acc[mt][nt][2 * hh] + b2.x, acc[mt][nt][2 * hh + 1] + b2.y);
            }
        }
}

// ---------------- launch ----------------
extern "C" void kernel_launch(void *const *d_in, const int *in_sizes, int n_in,
                              void *d_out, int out_size) {
    const float *Q = (const float *)d_in[0];
    const float *K = (const float *)d_in[1];
    const float *V = (const float *)d_in[2];
    const float *Wq = (const float *)d_in[3];
    const float *bq = (const float *)d_in[4];
    const float *Wk = (const float *)d_in[5];
    const float *bk = (const float *)d_in[6];
    const float *Wv = (const float *)d_in[7];
    const float *bv = (const float *)d_in[8];
    const float *Wo = (const float *)d_in[9];
    const float *bo = (const float *)d_in[10];
    float *out = (float *)d_out;

    proj_mm<<<dim3(NM / 128, NH, 3), 256>>>(Q, K, V, Wq, bq, Wk, bk, Wv, bv);
    scores_mm<<<dim3(NL / 128, NL / 64, NBH), 256>>>();
    colsum_mm<<<dim3(NL / 2 / 256, NBH), 256>>>();
    pv_mm<<<dim3(NL / 128, NBH), 256>>>();
    out_mm<<<dim3(NM / 128, NDM / 64), 256>>>(Wo, bo, out);
}

// round 4
// speedup vs baseline: 3.1476x; 1.1511x over previous
#include <cuda_runtime.h>
#include <cuda_bf16.h>
#include <cstdint>

#define NB 2
#define NL 2048
#define NDM 1024
#define NH 16
#define NDK 64
#define NBH 32
#define NM 4096

// ---------------- device scratch (alloc-free) ----------------
__device__ __align__(128) __nv_bfloat16 g_Qhi[NBH * NL * NDK];
__device__ __align__(128) __nv_bfloat16 g_Qlo[NBH * NL * NDK];
__device__ __align__(128) __nv_bfloat16 g_Khi[NBH * NL * NDK];
__device__ __align__(128) __nv_bfloat16 g_Klo[NBH * NL * NDK];
__device__ __align__(128) float g_Vp[NBH * NL * NDK];
__device__ __align__(128) __nv_bfloat16 g_VThi[NBH * NDK * NL];  // [bh][v][s], Zr-scaled
__device__ __align__(128) __nv_bfloat16 g_VTlo[NBH * NDK * NL];
__device__ __align__(128) float g_Z[NBH * NL];
__device__ __align__(128) __nv_bfloat16 g_Ohi[(size_t)NM * NDM];
__device__ __align__(128) __nv_bfloat16 g_Olo[(size_t)NM * NDM];
__device__ __align__(128) __nv_bfloat16 g_WThi[3 * NH * NDK * NDM];  // [w][h][k][m]
__device__ __align__(128) __nv_bfloat16 g_WTlo[3 * NH * NDK * NDM];
__device__ __align__(128) __nv_bfloat16 g_WoThi[NDM * NDM];  // [n][k] = Wo[k][n]
__device__ __align__(128) __nv_bfloat16 g_WoTlo[NDM * NDM];

// ---------------- PTX helpers ----------------
__device__ __forceinline__ uint32_t s2u(const void *p) {
    uint32_t a;
    asm("{ .reg .u64 t; cvta.to.shared.u64 t, %1; cvt.u32.u64 %0, t; }" : "=r"(a) : "l"(p));
    return a;
}
__device__ __forceinline__ uint32_t swz(uint32_t o) { return o ^ ((o >> 3) & 0x70); }

__device__ __forceinline__ void ldsm4(uint32_t r[4], uint32_t addr) {
    asm volatile("ldmatrix.sync.aligned.m8n8.x4.shared.b16 {%0,%1,%2,%3}, [%4];"
                 : "=r"(r[0]), "=r"(r[1]), "=r"(r[2]), "=r"(r[3]) : "r"(addr));
}
__device__ __forceinline__ void mma16816(float d[4], const uint32_t a[4], uint32_t b0, uint32_t b1) {
    asm volatile("mma.sync.aligned.m16n8k16.row.col.f32.bf16.bf16.f32 "
                 "{%0,%1,%2,%3}, {%4,%5,%6,%7}, {%8,%9}, {%0,%1,%2,%3};"
                 : "+f"(d[0]), "+f"(d[1]), "+f"(d[2]), "+f"(d[3])
                 : "r"(a[0]), "r"(a[1]), "r"(a[2]), "r"(a[3]), "r"(b0), "r"(b1));
}
#define CPA_COMMIT() asm volatile("cp.async.commit_group;")
#define CPA_WAIT1() asm volatile("cp.async.wait_group 1;")
#define CPA_WAIT0() asm volatile("cp.async.wait_group 0;")

// ---------------- math ----------------
__device__ __forceinline__ float fast_exp(float x) {
    float t = x * 1.4426950408889634f;
    t = fmaxf(t, -126.0f);
    float r = t + 12582912.0f;
    int i = __float_as_int(r);
    float f = t - (r - 12582912.0f);
    float p = 1.33335581e-3f;
    p = fmaf(p, f, 9.61812911e-3f);
    p = fmaf(p, f, 5.55041087e-2f);
    p = fmaf(p, f, 2.40226507e-1f);
    p = fmaf(p, f, 6.93147180e-1f);
    p = fmaf(p, f, 1.0f);
    return __int_as_float(__float_as_int(p) + (i << 23));
}
__device__ __forceinline__ void packsplit2(float x0, float x1, uint32_t &hi, uint32_t &lo) {
    __nv_bfloat162 hb = __floats2bfloat162_rn(x0, x1);
    float2 hf = __bfloat1622float2(hb);
    __nv_bfloat162 lb = __floats2bfloat162_rn(x0 - hf.x, x1 - hf.y);
    hi = *(uint32_t *)&hb;
    lo = *(uint32_t *)&lb;
}

// ---------------- tile loaders ----------------
// plain copy of R rows x 64 cols bf16 into swizzled smem
__device__ __forceinline__ void cp_tile(uint32_t dst, const __nv_bfloat16 *__restrict__ src,
                                        int rows, size_t ld, int tid) {
    for (int s = tid; s < rows * 8; s += 256) {
        int r = s >> 3, c8 = (s & 7) << 3;
        uint4 v = *(const uint4 *)(src + (size_t)r * ld + c8);
        asm volatile("st.shared.v4.b32 [%0], {%1,%2,%3,%4};"
                     ::"r"(dst + swz((uint32_t)(r * 128 + c8 * 2))), "r"(v.x), "r"(v.y), "r"(v.z), "r"(v.w));
    }
}
// cp.async copy of 64 rows x 64 cols bf16
__device__ __forceinline__ void cpa_tile(uint32_t dst, const __nv_bfloat16 *__restrict__ src,
                                         size_t ld, int tid) {
    for (int s = tid; s < 512; s += 256) {
        int r = s >> 3, c8 = (s & 7) << 3;
        asm volatile("cp.async.ca.shared.global [%0], [%1], 16;"
                     ::"r"(dst + swz((uint32_t)(r * 128 + c8 * 2))), "l"(src + (size_t)r * ld + c8));
    }
}
// split fp32 -> hi/lo bf16 smem tiles (R rows x 64 cols)
__device__ __forceinline__ void split8_sts(uint32_t dhi, uint32_t dlo, const float f[8]) {
    uint32_t h[4], l[4];
#pragma unroll
    for (int i = 0; i < 4; ++i) packsplit2(f[2 * i], f[2 * i + 1], h[i], l[i]);
    asm volatile("st.shared.v4.b32 [%0], {%1,%2,%3,%4};" ::"r"(dhi), "r"(h[0]), "r"(h[1]), "r"(h[2]), "r"(h[3]));
    asm volatile("st.shared.v4.b32 [%0], {%1,%2,%3,%4};" ::"r"(dlo), "r"(l[0]), "r"(l[1]), "r"(l[2]), "r"(l[3]));
}
template <int R>
__device__ __forceinline__ void load_split_rows(uint32_t sb_hi, uint32_t sb_lo,
                                                const float *__restrict__ src, int ldm, int tid) {
    for (int s = tid; s < R * 8; s += 256) {
        int r = s >> 3, c8 = (s & 7) << 3;
        const float4 *p = (const float4 *)(src + (size_t)r * ldm + c8);
        float4 f0 = p[0], f1 = p[1];
        float f[8] = {f0.x, f0.y, f0.z, f0.w, f1.x, f1.y, f1.z, f1.w};
        uint32_t off = swz((uint32_t)(r * 128 + c8 * 2));
        split8_sts(sb_hi + off, sb_lo + off, f);
    }
}

// ---------------- fragment loads ----------------
// A frag 16x16 at q-row base qb, k-chunk kc
__device__ __forceinline__ void ldA16(uint32_t tb, int lane, int qb, int kc, uint32_t a[4]) {
    int g = lane >> 3, l7 = lane & 7;
    uint32_t row = (uint32_t)(qb + ((g & 1) << 3) + l7);
    uint32_t kb = ((uint32_t)(((g >> 1) << 4) + kc * 32)) ^ ((uint32_t)l7 << 4);
    ldsm4(a, tb + row * 128 + kb);
}
// B frags: 64-wide n, k-chunk kc -> b0[8] (k lo), b1[8] (k hi)
__device__ __forceinline__ void ldB64(uint32_t tb, int lane, int kc, uint32_t b0[8], uint32_t b1[8]) {
    int g = lane >> 3, l7 = lane & 7;
    uint32_t xr = (uint32_t)l7 << 4;
    uint32_t r0 = tb + (uint32_t)(g * 8 + l7) * 128;
    uint32_t k0 = ((uint32_t)(kc * 32)) ^ xr;
    uint32_t k1 = ((uint32_t)(kc * 32 + 16)) ^ xr;
    ldsm4(b0, r0 + k0);
    ldsm4(b1, r0 + k1);
    ldsm4(b0 + 4, r0 + 4096 + k0);
    ldsm4(b1 + 4, r0 + 4096 + k1);
}
// 16q x 64s MMA (3 split passes), per-warp
__device__ __forceinline__ void mma1_64(uint32_t qhi, uint32_t qlo, uint32_t khi, uint32_t klo,
                                        int lane, int qb, float acc[8][4]) {
#pragma unroll
    for (int kc = 0; kc < 4; ++kc) {
        uint32_t ah[4], al[4];
        ldA16(qhi, lane, qb, kc, ah);
        ldA16(qlo, lane, qb, kc, al);
        uint32_t bh0[8], bh1[8], bl0[8], bl1[8];
        ldB64(khi, lane, kc, bh0, bh1);
        ldB64(klo, lane, kc, bl0, bl1);
#pragma unroll
        for (int nt = 0; nt < 8; ++nt) {
            mma16816(acc[nt], ah, bh0[nt], bh1[nt]);
            mma16816(acc[nt], ah, bl0[nt], bl1[nt]);
            mma16816(acc[nt], al, bh0[nt], bh1[nt]);
        }
    }
}

// ---------------- 8-warp 128x64 block GEMM core (proj/out) ----------------
#define OFF_AHI 0
#define OFF_ALO 16384
#define OFF_BHI 32768
#define OFF_BLO 40960
__device__ __forceinline__ void mma_tile(uint32_t sb, int lane, int wm, int wn, float acc[2][4][4]) {
    const uint32_t xr = (uint32_t)(lane & 7) << 4;
    const int g = lane >> 3;
    const int arow = ((g & 1) << 3) + (lane & 7);
    const uint32_t akh = (uint32_t)((g & 2) << 3);
    const uint32_t aA = (uint32_t)(wm * 32 + arow) * 128;
    const uint32_t aAhi = sb + OFF_AHI + aA, aAlo = sb + OFF_ALO + aA;
    const uint32_t aB = (uint32_t)(wn * 32 + g * 8 + (lane & 7)) * 128;
    const uint32_t aBhi = sb + OFF_BHI + aB, aBlo = sb + OFF_BLO + aB;
#pragma unroll
    for (int kk = 0; kk < 4; ++kk) {
        const uint32_t ka = ((uint32_t)(kk * 32) + akh) ^ xr;
        const uint32_t kb0 = ((uint32_t)(kk * 32)) ^ xr;
        const uint32_t kb1 = ((uint32_t)(kk * 32 + 16)) ^ xr;
        uint32_t ah0[4], ah1[4], al0[4], al1[4];
        ldsm4(ah0, aAhi + ka);
        ldsm4(ah1, aAhi + 2048 + ka);
        ldsm4(al0, aAlo + ka);
        ldsm4(al1, aAlo + 2048 + ka);
        uint32_t bh0[4], bh1[4], bl0[4], bl1[4];
        ldsm4(bh0, aBhi + kb0);
        ldsm4(bh1, aBhi + kb1);
        ldsm4(bl0, aBlo + kb0);
        ldsm4(bl1, aBlo + kb1);
#pragma unroll
        for (int nt = 0; nt < 4; ++nt) {
            mma16816(acc[0][nt], ah0, bh0[nt], bh1[nt]);
            mma16816(acc[1][nt], ah1, bh0[nt], bh1[nt]);
            mma16816(acc[0][nt], ah0, bl0[nt], bl1[nt]);
            mma16816(acc[1][nt], ah1, bl0[nt], bl1[nt]);
            mma16816(acc[0][nt], al0, bh0[nt], bh1[nt]);
            mma16816(acc[1][nt], al1, bh0[nt], bh1[nt]);
        }
    }
}
#define ACC_ZERO2(acc)                                                   \
    do {                                                                 \
        _Pragma("unroll") for (int _m = 0; _m < 2; ++_m)                 \
            _Pragma("unroll") for (int _n = 0; _n < 4; ++_n)             \
                _Pragma("unroll") for (int _i = 0; _i < 4; ++_i) acc[_m][_n][_i] = 0.f; \
    } while (0)

// ---------------- prep: split-transpose weights ----------------
__global__ void __launch_bounds__(256) prep_wqkv(const float *__restrict__ Wq,
                                                 const float *__restrict__ Wk,
                                                 const float *__restrict__ Wv) {
    __shared__ float ts[64][65];
    const int tid = threadIdx.x;
    const int mc = blockIdx.x, h = blockIdx.y, w = blockIdx.z;
    const float *W = (w == 0) ? Wq : (w == 1) ? Wk : Wv;
    const float *Wb = W + ((size_t)h * NDM + mc * 64) * NDK;
#pragma unroll
    for (int i = 0; i < 4; ++i) {
        int idx = tid + i * 256;
        int r = idx >> 4, c4 = (idx & 15) * 4;
        float4 v = *(const float4 *)(Wb + (size_t)r * NDK + c4);
        ts[r][c4] = v.x; ts[r][c4 + 1] = v.y; ts[r][c4 + 2] = v.z; ts[r][c4 + 3] = v.w;
    }
    __syncthreads();
    __nv_bfloat16 *Th = g_WThi + (size_t)(w * NH + h) * NDK * NDM + mc * 64;
    __nv_bfloat16 *Tl = g_WTlo + (size_t)(w * NH + h) * NDK * NDM + mc * 64;
#pragma unroll
    for (int i = 0; i < 8; ++i) {
        int idx = tid + i * 256;
        int k = idx >> 5, mp = (idx & 31) * 2;
        uint32_t hi, lo;
        packsplit2(ts[mp][k], ts[mp + 1][k], hi, lo);
        *(uint32_t *)(Th + (size_t)k * NDM + mp) = hi;
        *(uint32_t *)(Tl + (size_t)k * NDM + mp) = lo;
    }
}
__global__ void __launch_bounds__(256) prep_wo(const float *__restrict__ Wo) {
    __shared__ float ts[64][65];
    const int tid = threadIdx.x;
    const int nc = blockIdx.x, kc = blockIdx.y;
    const float *Wb = Wo + (size_t)kc * 64 * NDM + nc * 64;
#pragma unroll
    for (int i = 0; i < 4; ++i) {
        int idx = tid + i * 256;
        int r = idx >> 4, c4 = (idx & 15) * 4;
        float4 v = *(const float4 *)(Wb + (size_t)r * NDM + c4);
        ts[r][c4] = v.x; ts[r][c4 + 1] = v.y; ts[r][c4 + 2] = v.z; ts[r][c4 + 3] = v.w;
    }
    __syncthreads();
    __nv_bfloat16 *Th = g_WoThi + (size_t)nc * 64 * NDM + kc * 64;
    __nv_bfloat16 *Tl = g_WoTlo + (size_t)nc * 64 * NDM + kc * 64;
#pragma unroll
    for (int i = 0; i < 8; ++i) {
        int idx = tid + i * 256;
        int n = idx >> 5, kp = (idx & 31) * 2;
        uint32_t hi, lo;
        packsplit2(ts[kp][n], ts[kp + 1][n], hi, lo);
        *(uint32_t *)(Th + (size_t)n * NDM + kp) = hi;
        *(uint32_t *)(Tl + (size_t)n * NDM + kp) = lo;
    }
}
__global__ void zeroZ() { g_Z[blockIdx.x * 1024 + threadIdx.x] = 0.0f; }

// ---------------- kernel 1: projections ----------------
__global__ void __launch_bounds__(256) proj_mm(const float *__restrict__ Q, const float *__restrict__ K,
                                               const float *__restrict__ V,
                                               const float *__restrict__ bq, const float *__restrict__ bk,
                                               const float *__restrict__ bv) {
    __shared__ char smem[49152];
    uint32_t sb = s2u(smem);
    const int tid = threadIdx.x, lane = tid & 31, wid = tid >> 5;
    const int wm = wid >> 1, wn = wid & 1;
    const int h = blockIdx.x;
    const int row0 = blockIdx.y * 128;
    const int wz = blockIdx.z;
    const float *X = (wz == 0) ? Q : (wz == 1) ? K : V;
    const float *bias = (wz == 0) ? bq : (wz == 1) ? bk : bv;
    const __nv_bfloat16 *WTh = g_WThi + (size_t)(wz * NH + h) * NDK * NDM;
    const __nv_bfloat16 *WTl = g_WTlo + (size_t)(wz * NH + h) * NDK * NDM;

    float acc[2][4][4];
    ACC_ZERO2(acc);
    for (int it = 0; it < 16; ++it) {
        __syncthreads();
        load_split_rows<128>(sb + OFF_AHI, sb + OFF_ALO, X + (size_t)row0 * NDM + it * 64, NDM, tid);
        cp_tile(sb + OFF_BHI, WTh + it * 64, 64, NDM, tid);
        cp_tile(sb + OFF_BLO, WTl + it * 64, 64, NDM, tid);
        __syncthreads();
        mma_tile(sb, lane, wm, wn, acc);
    }
    const int trow = lane >> 2, tc = (lane & 3) * 2;
#pragma unroll
    for (int mt = 0; mt < 2; ++mt)
#pragma unroll
        for (int nt = 0; nt < 4; ++nt) {
            int col = wn * 32 + nt * 8 + tc;
            float2 b2 = *(const float2 *)(bias + h * NDK + col);
#pragma unroll
            for (int hh = 0; hh < 2; ++hh) {
                int grow = row0 + wm * 32 + mt * 16 + trow + hh * 8;
                int bb = grow >> 11, l = grow & (NL - 1);
                size_t off = ((size_t)(bb * NH + h) * NL + l) * NDK + col;
                float x0 = acc[mt][nt][2 * hh] + b2.x, x1 = acc[mt][nt][2 * hh + 1] + b2.y;
                if (wz == 2) {
                    *(float2 *)(g_Vp + off) = make_float2(x0, x1);
                } else {
                    uint32_t hi, lo;
                    packsplit2(x0, x1, hi, lo);
                    if (wz == 0) {
                        *(uint32_t *)(g_Qhi + off) = hi;
                        *(uint32_t *)(g_Qlo + off) = lo;
                    } else {
                        *(uint32_t *)(g_Khi + off) = hi;
                        *(uint32_t *)(g_Klo + off) = lo;
                    }
                }
            }
        }
}

// ---------------- kernel 2 (phase 1): column sums of exp(S) ----------------
#define P1_SMEM 65536
__global__ void __launch_bounds__(256, 2) phase1_mm() {
    extern __shared__ char smem[];
    uint32_t sb = s2u(smem);
    const int tid = threadIdx.x, lane = tid & 31, wid = tid >> 5;
    const int q0 = blockIdx.x * 128, bh = blockIdx.y;
    const __nv_bfloat16 *Kh = g_Khi + (size_t)bh * NL * NDK;
    const __nv_bfloat16 *Kl = g_Klo + (size_t)bh * NL * NDK;
    const uint32_t QHI = sb, QLO = sb + 16384, KST = sb + 32768;
    cp_tile(QHI, g_Qhi + ((size_t)bh * NL + q0) * NDK, 128, NDK, tid);
    cp_tile(QLO, g_Qlo + ((size_t)bh * NL + q0) * NDK, 128, NDK, tid);
    cpa_tile(KST, Kh, NDK, tid);
    cpa_tile(KST + 8192, Kl, NDK, tid);
    CPA_COMMIT();
    float *Zp = g_Z + (size_t)bh * NL;
    for (int it = 0; it < 32; ++it) {
        if (it < 31) {
            uint32_t st = KST + (uint32_t)(((it + 1) & 1) * 16384);
            cpa_tile(st, Kh + (size_t)(it + 1) * 64 * NDK, NDK, tid);
            cpa_tile(st + 8192, Kl + (size_t)(it + 1) * 64 * NDK, NDK, tid);
            CPA_COMMIT();
            CPA_WAIT1();
        } else {
            CPA_WAIT0();
        }
        __syncthreads();
        float acc[8][4];
#pragma unroll
        for (int nt = 0; nt < 8; ++nt)
#pragma unroll
            for (int i = 0; i < 4; ++i) acc[nt][i] = 0.f;
        const uint32_t KH = KST + (uint32_t)((it & 1) * 16384);
        mma1_64(QHI, QLO, KH, KH + 8192, lane, wid * 16, acc);
        float *zcol = Zp + it * 64;
#pragma unroll
        for (int nt = 0; nt < 8; ++nt) {
            float e0 = fast_exp(acc[nt][0] * 0.125f);
            float e1 = fast_exp(acc[nt][1] * 0.125f);
            float e2 = fast_exp(acc[nt][2] * 0.125f);
            float e3 = fast_exp(acc[nt][3] * 0.125f);
            float c0 = e0 + e2, c1 = e1 + e3;
#pragma unroll
            for (int o = 4; o < 32; o <<= 1) {
                c0 += __shfl_xor_sync(0xffffffffu, c0, o);
                c1 += __shfl_xor_sync(0xffffffffu, c1, o);
            }
            if (lane < 4) {
                atomicAdd(zcol + nt * 8 + lane * 2, c0);
                atomicAdd(zcol + nt * 8 + lane * 2 + 1, c1);
            }
        }
        __syncthreads();
    }
}

// ---------------- kernel 3: V' = (V * 1/Z) transposed + split ----------------
__global__ void __launch_bounds__(256) vsplit_mm() {
    __shared__ float ts[64][65];
    __shared__ float rz[64];
    const int tid = threadIdx.x;
    const int s0 = blockIdx.x * 64, bh = blockIdx.y;
    const float *Vb = g_Vp + ((size_t)bh * NL + s0) * NDK;
#pragma unroll
    for (int i = 0; i < 4; ++i) {
        int idx = tid + i * 256;
        int r = idx >> 4, c4 = (idx & 15) * 4;
        float4 v = *(const float4 *)(Vb + (size_t)r * NDK + c4);
        ts[r][c4] = v.x; ts[r][c4 + 1] = v.y; ts[r][c4 + 2] = v.z; ts[r][c4 + 3] = v.w;
    }
    if (tid < 64) rz[tid] = 1.0f / g_Z[(size_t)bh * NL + s0 + tid];
    __syncthreads();
    __nv_bfloat16 *Oh = g_VThi + (size_t)bh * NDK * NL + s0;
    __nv_bfloat16 *Ol = g_VTlo + (size_t)bh * NDK * NL + s0;
#pragma unroll
    for (int i = 0; i < 8; ++i) {
        int idx = tid + i * 256;
        int v = idx >> 5, sp = (idx & 31) * 2;
        float x0 = ts[sp][v] * rz[sp];
        float x1 = ts[sp + 1][v] * rz[sp + 1];
        uint32_t hi, lo;
        packsplit2(x0, x1, hi, lo);
        *(uint32_t *)(Oh + (size_t)v * NL + sp) = hi;
        *(uint32_t *)(Ol + (size_t)v * NL + sp) = lo;
    }
}

// ---------------- kernel 4 (phase 2): O = exp(S)·V' fused ----------------
#define P2_SMEM 98304
__global__ void __launch_bounds__(256, 2) attn_mm() {
    extern __shared__ char smem[];
    uint32_t sb = s2u(smem);
    const int tid = threadIdx.x, lane = tid & 31, wid = tid >> 5;
    const int q0 = blockIdx.x * 128, bh = blockIdx.y;
    const int bb = bh >> 4, h = bh & 15;
    const __nv_bfloat16 *Kh = g_Khi + (size_t)bh * NL * NDK;
    const __nv_bfloat16 *Kl = g_Klo + (size_t)bh * NL * NDK;
    const __nv_bfloat16 *Vh = g_VThi + (size_t)bh * NDK * NL;
    const __nv_bfloat16 *Vl = g_VTlo + (size_t)bh * NDK * NL;
    const uint32_t QHI = sb, QLO = sb + 16384, ST = sb + 32768;
    cp_tile(QHI, g_Qhi + ((size_t)bh * NL + q0) * NDK, 128, NDK, tid);
    cp_tile(QLO, g_Qlo + ((size_t)bh * NL + q0) * NDK, 128, NDK, tid);
    cpa_tile(ST, Kh, NDK, tid);
    cpa_tile(ST + 8192, Kl, NDK, tid);
    cpa_tile(ST + 16384, Vh, NL, tid);
    cpa_tile(ST + 24576, Vl, NL, tid);
    CPA_COMMIT();

    float oacc[8][4];
#pragma unroll
    for (int vt = 0; vt < 8; ++vt)
#pragma unroll
        for (int i = 0; i < 4; ++i) oacc[vt][i] = 0.f;

    for (int it = 0; it < 32; ++it) {
        if (it < 31) {
            uint32_t st = ST + (uint32_t)(((it + 1) & 1) * 32768);
            cpa_tile(st, Kh + (size_t)(it + 1) * 64 * NDK, NDK, tid);
            cpa_tile(st + 8192, Kl + (size_t)(it + 1) * 64 * NDK, NDK, tid);
            cpa_tile(st + 16384, Vh + (size_t)(it + 1) * 64, NL, tid);
            cpa_tile(st + 24576, Vl + (size_t)(it + 1) * 64, NL, tid);
            CPA_COMMIT();
            CPA_WAIT1();
        } else {
            CPA_WAIT0();
        }
        __syncthreads();
        const uint32_t SS = ST + (uint32_t)((it & 1) * 32768);
        float acc[8][4];
#pragma unroll
        for (int nt = 0; nt < 8; ++nt)
#pragma unroll
            for (int i = 0; i < 4; ++i) acc[nt][i] = 0.f;
        mma1_64(QHI, QLO, SS, SS + 8192, lane, wid * 16, acc);
        // exp + in-register conversion to A frags, then MMA2 vs V'
#pragma unroll
        for (int kc2 = 0; kc2 < 4; ++kc2) {
            const int a = 2 * kc2, b = a + 1;
            float ea0 = fast_exp(acc[a][0] * 0.125f), ea1 = fast_exp(acc[a][1] * 0.125f);
            float ea2 = fast_exp(acc[a][2] * 0.125f), ea3 = fast_exp(acc[a][3] * 0.125f);
            float eb0 = fast_exp(acc[b][0] * 0.125f), eb1 = fast_exp(acc[b][1] * 0.125f);
            float eb2 = fast_exp(acc[b][2] * 0.125f), eb3 = fast_exp(acc[b][3] * 0.125f);
            uint32_t pah[4], pal[4];
            packsplit2(ea0, ea1, pah[0], pal[0]);
            packsplit2(ea2, ea3, pah[1], pal[1]);
            packsplit2(eb0, eb1, pah[2], pal[2]);
            packsplit2(eb2, eb3, pah[3], pal[3]);
            uint32_t vh0[8], vh1[8], vl0[8], vl1[8];
            ldB64(SS + 16384, lane, kc2, vh0, vh1);
            ldB64(SS + 24576, lane, kc2, vl0, vl1);
#pragma unroll
            for (int vt = 0; vt < 8; ++vt) {
                mma16816(oacc[vt], pah, vh0[vt], vh1[vt]);
                mma16816(oacc[vt], pah, vl0[vt], vl1[vt]);
                mma16816(oacc[vt], pal, vh0[vt], vh1[vt]);
            }
        }
        __syncthreads();
    }
    // epilogue: split-store O
    const int r = lane >> 2, c2 = (lane & 3) * 2;
    const size_t row0 = ((size_t)bb * NL + q0 + wid * 16 + r) * NDM + h * NDK;
    const size_t row1 = row0 + 8 * NDM;
#pragma unroll
    for (int vt = 0; vt < 8; ++vt) {
        int col = vt * 8 + c2;
        uint32_t hi, lo;
        packsplit2(oacc[vt][0], oacc[vt][1], hi, lo);
        *(uint32_t *)(g_Ohi + row0 + col) = hi;
        *(uint32_t *)(g_Olo + row0 + col) = lo;
        packsplit2(oacc[vt][2], oacc[vt][3], hi, lo);
        *(uint32_t *)(g_Ohi + row1 + col) = hi;
        *(uint32_t *)(g_Olo + row1 + col) = lo;
    }
}

// ---------------- kernel 5: out = cat_V @ Wo + bo ----------------
__global__ void __launch_bounds__(256) out_mm(const float *__restrict__ bo, float *__restrict__ out) {
    __shared__ char smem[49152];
    uint32_t sb = s2u(smem);
    const int tid = threadIdx.x, lane = tid & 31, wid = tid >> 5;
    const int wm = wid >> 1, wn = wid & 1;
    const int row0 = blockIdx.x * 128;
    const int n0 = blockIdx.y * 64;

    float acc[2][4][4];
    ACC_ZERO2(acc);
    for (int it = 0; it < 16; ++it) {
        __syncthreads();
        cp_tile(sb + OFF_AHI, g_Ohi + (size_t)row0 * NDM + it * 64, 128, NDM, tid);
        cp_tile(sb + OFF_ALO, g_Olo + (size_t)row0 * NDM + it * 64, 128, NDM, tid);
        cp_tile(sb + OFF_BHI, g_WoThi + (size_t)n0 * NDM + it * 64, 64, NDM, tid);
        cp_tile(sb + OFF_BLO, g_WoTlo + (size_t)n0 * NDM + it * 64, 64, NDM, tid);
        __syncthreads();
        mma_tile(sb, lane, wm, wn, acc);
    }
    const int trow = lane >> 2, tc = (lane & 3) * 2;
#pragma unroll
    for (int mt = 0; mt < 2; ++mt)
#pragma unroll
        for (int nt = 0; nt < 4; ++nt) {
            int col = n0 + wn * 32 + nt * 8 + tc;
            float2 b2 = *(const float2 *)(bo + col);
#pragma unroll
            for (int hh = 0; hh < 2; ++hh) {
                int row = row0 + wm * 32 + mt * 16 + trow + hh * 8;
                *(float2 *)(out + (size_t)row * NDM + col) =
                    make_float2(acc[mt][nt][2 * hh] + b2.x, acc[mt][nt][2 * hh + 1] + b2.y);
            }
        }
}

// ---------------- launch ----------------
extern "C" void kernel_launch(void *const *d_in, const int *in_sizes, int n_in,
                              void *d_out, int out_size) {
    const float *Q = (const float *)d_in[0];
    const float *K = (const float *)d_in[1];
    const float *V = (const float *)d_in[2];
    const float *Wq = (const float *)d_in[3];
    const float *bq = (const float *)d_in[4];
    const float *Wk = (const float *)d_in[5];
    const float *bk = (const float *)d_in[6];
    const float *Wv = (const float *)d_in[7];
    const float *bv = (const float *)d_in[8];
    const float *Wo = (const float *)d_in[9];
    const float *bo = (const float *)d_in[10];
    float *out = (float *)d_out;

    cudaFuncSetAttribute(phase1_mm, cudaFuncAttributeMaxDynamicSharedMemorySize, P1_SMEM);
    cudaFuncSetAttribute(attn_mm, cudaFuncAttributeMaxDynamicSharedMemorySize, P2_SMEM);

    prep_wqkv<<<dim3(16, NH, 3), 256>>>(Wq, Wk, Wv);
    prep_wo<<<dim3(16, 16), 256>>>(Wo);
    zeroZ<<<64, 1024>>>();
    proj_mm<<<dim3(NH, NM / 128, 3), 256>>>(Q, K, V, bq, bk, bv);
    phase1_mm<<<dim3(NL / 128, NBH), 256, P1_SMEM>>>();
    vsplit_mm<<<dim3(NL / 64, NBH), 256>>>();
    attn_mm<<<dim3(NL / 128, NBH), 256, P2_SMEM>>>();
    out_mm<<<dim3(NM / 128, NDM / 64), 256>>>(bo, out);
}

// round 5
// speedup vs baseline: 4.1121x; 1.3064x over previous
#include <cuda_runtime.h>
#include <cuda_bf16.h>
#include <cstdint>

#define NB 2
#define NL 2048
#define NDM 1024
#define NH 16
#define NDK 64
#define NBH 32
#define NM 4096

// ---------------- device scratch (alloc-free) ----------------
__device__ __align__(128) __nv_bfloat16 g_Xhi[3][(size_t)NM * NDM];  // pre-split inputs
__device__ __align__(128) __nv_bfloat16 g_Xlo[3][(size_t)NM * NDM];
__device__ __align__(128) __nv_bfloat16 g_Qhi[NBH * NL * NDK];
__device__ __align__(128) __nv_bfloat16 g_Qlo[NBH * NL * NDK];
__device__ __align__(128) __nv_bfloat16 g_Khi[NBH * NL * NDK];
__device__ __align__(128) __nv_bfloat16 g_Klo[NBH * NL * NDK];
__device__ __align__(128) float g_Vp[NBH * NL * NDK];
__device__ __align__(128) __nv_bfloat16 g_VThi[NBH * NDK * NL];  // [bh][v][s], Zr-scaled
__device__ __align__(128) __nv_bfloat16 g_VTlo[NBH * NDK * NL];
__device__ __align__(128) float g_Z[NBH * NL];
__device__ __align__(128) __nv_bfloat16 g_Ohi[(size_t)NM * NDM];
__device__ __align__(128) __nv_bfloat16 g_Olo[(size_t)NM * NDM];
__device__ __align__(128) __nv_bfloat16 g_WThi[3 * NH * NDK * NDM];  // [w][h][k][m]
__device__ __align__(128) __nv_bfloat16 g_WTlo[3 * NH * NDK * NDM];
__device__ __align__(128) __nv_bfloat16 g_WoThi[NDM * NDM];  // [n][k] = Wo[k][n]
__device__ __align__(128) __nv_bfloat16 g_WoTlo[NDM * NDM];

// ---------------- PTX helpers ----------------
__device__ __forceinline__ uint32_t s2u(const void *p) {
    uint32_t a;
    asm("{ .reg .u64 t; cvta.to.shared.u64 t, %1; cvt.u32.u64 %0, t; }" : "=r"(a) : "l"(p));
    return a;
}
__device__ __forceinline__ uint32_t swz(uint32_t o) { return o ^ ((o >> 3) & 0x70); }

__device__ __forceinline__ void ldsm4(uint32_t r[4], uint32_t addr) {
    asm volatile("ldmatrix.sync.aligned.m8n8.x4.shared.b16 {%0,%1,%2,%3}, [%4];"
                 : "=r"(r[0]), "=r"(r[1]), "=r"(r[2]), "=r"(r[3]) : "r"(addr));
}
__device__ __forceinline__ void mma16816(float d[4], const uint32_t a[4], uint32_t b0, uint32_t b1) {
    asm volatile("mma.sync.aligned.m16n8k16.row.col.f32.bf16.bf16.f32 "
                 "{%0,%1,%2,%3}, {%4,%5,%6,%7}, {%8,%9}, {%0,%1,%2,%3};"
                 : "+f"(d[0]), "+f"(d[1]), "+f"(d[2]), "+f"(d[3])
                 : "r"(a[0]), "r"(a[1]), "r"(a[2]), "r"(a[3]), "r"(b0), "r"(b1));
}
#define CPA_COMMIT() asm volatile("cp.async.commit_group;")
#define CPA_WAIT1() asm volatile("cp.async.wait_group 1;")
#define CPA_WAIT0() asm volatile("cp.async.wait_group 0;")

// ---------------- math ----------------
__device__ __forceinline__ float fast_exp(float x) {
    float t = x * 1.4426950408889634f;
    t = fmaxf(t, -126.0f);
    float r = t + 12582912.0f;
    int i = __float_as_int(r);
    float f = t - (r - 12582912.0f);
    float p = 1.33335581e-3f;
    p = fmaf(p, f, 9.61812911e-3f);
    p = fmaf(p, f, 5.55041087e-2f);
    p = fmaf(p, f, 2.40226507e-1f);
    p = fmaf(p, f, 6.93147180e-1f);
    p = fmaf(p, f, 1.0f);
    return __int_as_float(__float_as_int(p) + (i << 23));
}
__device__ __forceinline__ void packsplit2(float x0, float x1, uint32_t &hi, uint32_t &lo) {
    __nv_bfloat162 hb = __floats2bfloat162_rn(x0, x1);
    float2 hf = __bfloat1622float2(hb);
    __nv_bfloat162 lb = __floats2bfloat162_rn(x0 - hf.x, x1 - hf.y);
    hi = *(uint32_t *)&hb;
    lo = *(uint32_t *)&lb;
}

// ---------------- tile loaders ----------------
__device__ __forceinline__ void cp_tile(uint32_t dst, const __nv_bfloat16 *__restrict__ src,
                                        int rows, size_t ld, int tid) {
    for (int s = tid; s < rows * 8; s += 256) {
        int r = s >> 3, c8 = (s & 7) << 3;
        uint4 v = *(const uint4 *)(src + (size_t)r * ld + c8);
        asm volatile("st.shared.v4.b32 [%0], {%1,%2,%3,%4};"
                     ::"r"(dst + swz((uint32_t)(r * 128 + c8 * 2))), "r"(v.x), "r"(v.y), "r"(v.z), "r"(v.w));
    }
}
template <int ROWS>
__device__ __forceinline__ void cpa_rows(uint32_t dst, const __nv_bfloat16 *__restrict__ src,
                                         size_t ld, int tid) {
#pragma unroll
    for (int s = tid; s < ROWS * 8; s += 256) {
        int r = s >> 3, c8 = (s & 7) << 3;
        asm volatile("cp.async.ca.shared.global [%0], [%1], 16;"
                     ::"r"(dst + swz((uint32_t)(r * 128 + c8 * 2))), "l"(src + (size_t)r * ld + c8));
    }
}

// ---------------- fragment loads ----------------
__device__ __forceinline__ void ldA16(uint32_t tb, int lane, int qb, int kc, uint32_t a[4]) {
    int g = lane >> 3, l7 = lane & 7;
    uint32_t row = (uint32_t)(qb + ((g & 1) << 3) + l7);
    uint32_t kb = ((uint32_t)(((g >> 1) << 4) + kc * 32)) ^ ((uint32_t)l7 << 4);
    ldsm4(a, tb + row * 128 + kb);
}
__device__ __forceinline__ void ldB64(uint32_t tb, int lane, int kc, uint32_t b0[8], uint32_t b1[8]) {
    int g = lane >> 3, l7 = lane & 7;
    uint32_t xr = (uint32_t)l7 << 4;
    uint32_t r0 = tb + (uint32_t)(g * 8 + l7) * 128;
    uint32_t k0 = ((uint32_t)(kc * 32)) ^ xr;
    uint32_t k1 = ((uint32_t)(kc * 32 + 16)) ^ xr;
    ldsm4(b0, r0 + k0);
    ldsm4(b1, r0 + k1);
    ldsm4(b0 + 4, r0 + 4096 + k0);
    ldsm4(b1 + 4, r0 + 4096 + k1);
}
__device__ __forceinline__ void mma1_64(uint32_t qhi, uint32_t qlo, uint32_t khi, uint32_t klo,
                                        int lane, int qb, float acc[8][4]) {
#pragma unroll
    for (int kc = 0; kc < 4; ++kc) {
        uint32_t ah[4], al[4];
        ldA16(qhi, lane, qb, kc, ah);
        ldA16(qlo, lane, qb, kc, al);
        uint32_t bh0[8], bh1[8], bl0[8], bl1[8];
        ldB64(khi, lane, kc, bh0, bh1);
        ldB64(klo, lane, kc, bl0, bl1);
#pragma unroll
        for (int nt = 0; nt < 8; ++nt) {
            mma16816(acc[nt], ah, bh0[nt], bh1[nt]);
            mma16816(acc[nt], ah, bl0[nt], bl1[nt]);
            mma16816(acc[nt], al, bh0[nt], bh1[nt]);
        }
    }
}

// ---------------- 8-warp 128x64 block GEMM core ----------------
#define OFF_AHI 0
#define OFF_ALO 16384
#define OFF_BHI 32768
#define OFF_BLO 40960
#define GBUF 49152
__device__ __forceinline__ void mma_tile(uint32_t sb, int lane, int wm, int wn, float acc[2][4][4]) {
    const uint32_t xr = (uint32_t)(lane & 7) << 4;
    const int g = lane >> 3;
    const int arow = ((g & 1) << 3) + (lane & 7);
    const uint32_t akh = (uint32_t)((g & 2) << 3);
    const uint32_t aA = (uint32_t)(wm * 32 + arow) * 128;
    const uint32_t aAhi = sb + OFF_AHI + aA, aAlo = sb + OFF_ALO + aA;
    const uint32_t aB = (uint32_t)(wn * 32 + g * 8 + (lane & 7)) * 128;
    const uint32_t aBhi = sb + OFF_BHI + aB, aBlo = sb + OFF_BLO + aB;
#pragma unroll
    for (int kk = 0; kk < 4; ++kk) {
        const uint32_t ka = ((uint32_t)(kk * 32) + akh) ^ xr;
        const uint32_t kb0 = ((uint32_t)(kk * 32)) ^ xr;
        const uint32_t kb1 = ((uint32_t)(kk * 32 + 16)) ^ xr;
        uint32_t ah0[4], ah1[4], al0[4], al1[4];
        ldsm4(ah0, aAhi + ka);
        ldsm4(ah1, aAhi + 2048 + ka);
        ldsm4(al0, aAlo + ka);
        ldsm4(al1, aAlo + 2048 + ka);
        uint32_t bh0[4], bh1[4], bl0[4], bl1[4];
        ldsm4(bh0, aBhi + kb0);
        ldsm4(bh1, aBhi + kb1);
        ldsm4(bl0, aBlo + kb0);
        ldsm4(bl1, aBlo + kb1);
#pragma unroll
        for (int nt = 0; nt < 4; ++nt) {
            mma16816(acc[0][nt], ah0, bh0[nt], bh1[nt]);
            mma16816(acc[1][nt], ah1, bh0[nt], bh1[nt]);
            mma16816(acc[0][nt], ah0, bl0[nt], bl1[nt]);
            mma16816(acc[1][nt], ah1, bl0[nt], bl1[nt]);
            mma16816(acc[0][nt], al0, bh0[nt], bh1[nt]);
            mma16816(acc[1][nt], al1, bh0[nt], bh1[nt]);
        }
    }
}
#define ACC_ZERO2(acc)                                                   \
    do {                                                                 \
        _Pragma("unroll") for (int _m = 0; _m < 2; ++_m)                 \
            _Pragma("unroll") for (int _n = 0; _n < 4; ++_n)             \
                _Pragma("unroll") for (int _i = 0; _i < 4; ++_i) acc[_m][_n][_i] = 0.f; \
    } while (0)

// ---------------- prep kernels ----------------
__global__ void __launch_bounds__(256) presplit(const float *__restrict__ Q,
                                                const float *__restrict__ K,
                                                const float *__restrict__ V) {
    const int z = blockIdx.y;
    const float *X = (z == 0) ? Q : (z == 1) ? K : V;
    size_t i8 = ((size_t)blockIdx.x * 256 + threadIdx.x) * 8;
    float4 a = *(const float4 *)(X + i8);
    float4 b = *(const float4 *)(X + i8 + 4);
    uint32_t h[4], l[4];
    packsplit2(a.x, a.y, h[0], l[0]);
    packsplit2(a.z, a.w, h[1], l[1]);
    packsplit2(b.x, b.y, h[2], l[2]);
    packsplit2(b.z, b.w, h[3], l[3]);
    *(uint4 *)(&g_Xhi[z][i8]) = make_uint4(h[0], h[1], h[2], h[3]);
    *(uint4 *)(&g_Xlo[z][i8]) = make_uint4(l[0], l[1], l[2], l[3]);
}
__global__ void __launch_bounds__(256) prep_wqkv(const float *__restrict__ Wq,
                                                 const float *__restrict__ Wk,
                                                 const float *__restrict__ Wv) {
    __shared__ float ts[64][65];
    const int tid = threadIdx.x;
    const int mc = blockIdx.x, h = blockIdx.y, w = blockIdx.z;
    const float *W = (w == 0) ? Wq : (w == 1) ? Wk : Wv;
    const float *Wb = W + ((size_t)h * NDM + mc * 64) * NDK;
#pragma unroll
    for (int i = 0; i < 4; ++i) {
        int idx = tid + i * 256;
        int r = idx >> 4, c4 = (idx & 15) * 4;
        float4 v = *(const float4 *)(Wb + (size_t)r * NDK + c4);
        ts[r][c4] = v.x; ts[r][c4 + 1] = v.y; ts[r][c4 + 2] = v.z; ts[r][c4 + 3] = v.w;
    }
    __syncthreads();
    __nv_bfloat16 *Th = g_WThi + (size_t)(w * NH + h) * NDK * NDM + mc * 64;
    __nv_bfloat16 *Tl = g_WTlo + (size_t)(w * NH + h) * NDK * NDM + mc * 64;
#pragma unroll
    for (int i = 0; i < 8; ++i) {
        int idx = tid + i * 256;
        int k = idx >> 5, mp = (idx & 31) * 2;
        uint32_t hi, lo;
        packsplit2(ts[mp][k], ts[mp + 1][k], hi, lo);
        *(uint32_t *)(Th + (size_t)k * NDM + mp) = hi;
        *(uint32_t *)(Tl + (size_t)k * NDM + mp) = lo;
    }
}
__global__ void __launch_bounds__(256) prep_wo(const float *__restrict__ Wo) {
    __shared__ float ts[64][65];
    const int tid = threadIdx.x;
    const int nc = blockIdx.x, kc = blockIdx.y;
    const float *Wb = Wo + (size_t)kc * 64 * NDM + nc * 64;
#pragma unroll
    for (int i = 0; i < 4; ++i) {
        int idx = tid + i * 256;
        int r = idx >> 4, c4 = (idx & 15) * 4;
        float4 v = *(const float4 *)(Wb + (size_t)r * NDM + c4);
        ts[r][c4] = v.x; ts[r][c4 + 1] = v.y; ts[r][c4 + 2] = v.z; ts[r][c4 + 3] = v.w;
    }
    __syncthreads();
    __nv_bfloat16 *Th = g_WoThi + (size_t)nc * 64 * NDM + kc * 64;
    __nv_bfloat16 *Tl = g_WoTlo + (size_t)nc * 64 * NDM + kc * 64;
#pragma unroll
    for (int i = 0; i < 8; ++i) {
        int idx = tid + i * 256;
        int n = idx >> 5, kp = (idx & 31) * 2;
        uint32_t hi, lo;
        packsplit2(ts[kp][n], ts[kp + 1][n], hi, lo);
        *(uint32_t *)(Th + (size_t)n * NDM + kp) = hi;
        *(uint32_t *)(Tl + (size_t)n * NDM + kp) = lo;
    }
}
__global__ void zeroZ() { g_Z[blockIdx.x * 1024 + threadIdx.x] = 0.0f; }

// ---------------- kernel 1: projections (pure-copy, double-buffered) ----------------
#define PJ_SMEM (2 * GBUF)
__global__ void __launch_bounds__(256, 2) proj_mm(const float *__restrict__ bq,
                                                  const float *__restrict__ bk,
                                                  const float *__restrict__ bv) {
    extern __shared__ char smem[];
    uint32_t sb = s2u(smem);
    const int tid = threadIdx.x, lane = tid & 31, wid = tid >> 5;
    const int wm = wid >> 1, wn = wid & 1;
    const int h = blockIdx.x;
    const int row0 = blockIdx.y * 128;
    const int wz = blockIdx.z;
    const float *bias = (wz == 0) ? bq : (wz == 1) ? bk : bv;
    const __nv_bfloat16 *Xh = g_Xhi[wz] + (size_t)row0 * NDM;
    const __nv_bfloat16 *Xl = g_Xlo[wz] + (size_t)row0 * NDM;
    const __nv_bfloat16 *WTh = g_WThi + (size_t)(wz * NH + h) * NDK * NDM;
    const __nv_bfloat16 *WTl = g_WTlo + (size_t)(wz * NH + h) * NDK * NDM;

    cpa_rows<128>(sb + OFF_AHI, Xh, NDM, tid);
    cpa_rows<128>(sb + OFF_ALO, Xl, NDM, tid);
    cpa_rows<64>(sb + OFF_BHI, WTh, NDM, tid);
    cpa_rows<64>(sb + OFF_BLO, WTl, NDM, tid);
    CPA_COMMIT();

    float acc[2][4][4];
    ACC_ZERO2(acc);
    for (int it = 0; it < 16; ++it) {
        if (it < 15) {
            uint32_t st = sb + (uint32_t)(((it + 1) & 1) * GBUF);
            cpa_rows<128>(st + OFF_AHI, Xh + (it + 1) * 64, NDM, tid);
            cpa_rows<128>(st + OFF_ALO, Xl + (it + 1) * 64, NDM, tid);
            cpa_rows<64>(st + OFF_BHI, WTh + (it + 1) * 64, NDM, tid);
            cpa_rows<64>(st + OFF_BLO, WTl + (it + 1) * 64, NDM, tid);
            CPA_COMMIT();
            CPA_WAIT1();
        } else {
            CPA_WAIT0();
        }
        __syncthreads();
        mma_tile(sb + (uint32_t)((it & 1) * GBUF), lane, wm, wn, acc);
        __syncthreads();
    }
    const int trow = lane >> 2, tc = (lane & 3) * 2;
#pragma unroll
    for (int mt = 0; mt < 2; ++mt)
#pragma unroll
        for (int nt = 0; nt < 4; ++nt) {
            int col = wn * 32 + nt * 8 + tc;
            float2 b2 = *(const float2 *)(bias + h * NDK + col);
#pragma unroll
            for (int hh = 0; hh < 2; ++hh) {
                int grow = row0 + wm * 32 + mt * 16 + trow + hh * 8;
                int bb = grow >> 11, l = grow & (NL - 1);
                size_t off = ((size_t)(bb * NH + h) * NL + l) * NDK + col;
                float x0 = acc[mt][nt][2 * hh] + b2.x, x1 = acc[mt][nt][2 * hh + 1] + b2.y;
                if (wz == 2) {
                    *(float2 *)(g_Vp + off) = make_float2(x0, x1);
                } else {
                    uint32_t hi, lo;
                    packsplit2(x0, x1, hi, lo);
                    if (wz == 0) {
                        *(uint32_t *)(g_Qhi + off) = hi;
                        *(uint32_t *)(g_Qlo + off) = lo;
                    } else {
                        *(uint32_t *)(g_Khi + off) = hi;
                        *(uint32_t *)(g_Klo + off) = lo;
                    }
                }
            }
        }
}

// ---------------- kernel 2 (phase 1): column sums of exp(S) ----------------
#define P1_SMEM 65536
__global__ void __launch_bounds__(256, 2) phase1_mm() {
    extern __shared__ char smem[];
    uint32_t sb = s2u(smem);
    const int tid = threadIdx.x, lane = tid & 31, wid = tid >> 5;
    const int q0 = blockIdx.x * 128, bh = blockIdx.y;
    const __nv_bfloat16 *Kh = g_Khi + (size_t)bh * NL * NDK;
    const __nv_bfloat16 *Kl = g_Klo + (size_t)bh * NL * NDK;
    const uint32_t QHI = sb, QLO = sb + 16384, KST = sb + 32768;
    cp_tile(QHI, g_Qhi + ((size_t)bh * NL + q0) * NDK, 128, NDK, tid);
    cp_tile(QLO, g_Qlo + ((size_t)bh * NL + q0) * NDK, 128, NDK, tid);
    cpa_rows<64>(KST, Kh, NDK, tid);
    cpa_rows<64>(KST + 8192, Kl, NDK, tid);
    CPA_COMMIT();
    float *Zp = g_Z + (size_t)bh * NL;
    for (int it = 0; it < 32; ++it) {
        if (it < 31) {
            uint32_t st = KST + (uint32_t)(((it + 1) & 1) * 16384);
            cpa_rows<64>(st, Kh + (size_t)(it + 1) * 64 * NDK, NDK, tid);
            cpa_rows<64>(st + 8192, Kl + (size_t)(it + 1) * 64 * NDK, NDK, tid);
            CPA_COMMIT();
            CPA_WAIT1();
        } else {
            CPA_WAIT0();
        }
        __syncthreads();
        float acc[8][4];
#pragma unroll
        for (int nt = 0; nt < 8; ++nt)
#pragma unroll
            for (int i = 0; i < 4; ++i) acc[nt][i] = 0.f;
        const uint32_t KH = KST + (uint32_t)((it & 1) * 16384);
        mma1_64(QHI, QLO, KH, KH + 8192, lane, wid * 16, acc);
        float *zcol = Zp + it * 64;
#pragma unroll
        for (int nt = 0; nt < 8; ++nt) {
            float e0 = fast_exp(acc[nt][0] * 0.125f);
            float e1 = fast_exp(acc[nt][1] * 0.125f);
            float e2 = fast_exp(acc[nt][2] * 0.125f);
            float e3 = fast_exp(acc[nt][3] * 0.125f);
            float c0 = e0 + e2, c1 = e1 + e3;
#pragma unroll
            for (int o = 4; o < 32; o <<= 1) {
                c0 += __shfl_xor_sync(0xffffffffu, c0, o);
                c1 += __shfl_xor_sync(0xffffffffu, c1, o);
            }
            if (lane < 4) {
                atomicAdd(zcol + nt * 8 + lane * 2, c0);
                atomicAdd(zcol + nt * 8 + lane * 2 + 1, c1);
            }
        }
        __syncthreads();
    }
}

// ---------------- kernel 3: V' = (V * 1/Z) transposed + split ----------------
__global__ void __launch_bounds__(256) vsplit_mm() {
    __shared__ float ts[64][65];
    __shared__ float rz[64];
    const int tid = threadIdx.x;
    const int s0 = blockIdx.x * 64, bh = blockIdx.y;
    const float *Vb = g_Vp + ((size_t)bh * NL + s0) * NDK;
#pragma unroll
    for (int i = 0; i < 4; ++i) {
        int idx = tid + i * 256;
        int r = idx >> 4, c4 = (idx & 15) * 4;
        float4 v = *(const float4 *)(Vb + (size_t)r * NDK + c4);
        ts[r][c4] = v.x; ts[r][c4 + 1] = v.y; ts[r][c4 + 2] = v.z; ts[r][c4 + 3] = v.w;
    }
    if (tid < 64) rz[tid] = 1.0f / g_Z[(size_t)bh * NL + s0 + tid];
    __syncthreads();
    __nv_bfloat16 *Oh = g_VThi + (size_t)bh * NDK * NL + s0;
    __nv_bfloat16 *Ol = g_VTlo + (size_t)bh * NDK * NL + s0;
#pragma unroll
    for (int i = 0; i < 8; ++i) {
        int idx = tid + i * 256;
        int v = idx >> 5, sp = (idx & 31) * 2;
        float x0 = ts[sp][v] * rz[sp];
        float x1 = ts[sp + 1][v] * rz[sp + 1];
        uint32_t hi, lo;
        packsplit2(x0, x1, hi, lo);
        *(uint32_t *)(Oh + (size_t)v * NL + sp) = hi;
        *(uint32_t *)(Ol + (size_t)v * NL + sp) = lo;
    }
}

// ---------------- kernel 4 (phase 2): O = exp(S)·V' fused ----------------
#define P2_SMEM 98304
__global__ void __launch_bounds__(256, 2) attn_mm() {
    extern __shared__ char smem[];
    uint32_t sb = s2u(smem);
    const int tid = threadIdx.x, lane = tid & 31, wid = tid >> 5;
    const int q0 = blockIdx.x * 128, bh = blockIdx.y;
    const int bb = bh >> 4, h = bh & 15;
    const __nv_bfloat16 *Kh = g_Khi + (size_t)bh * NL * NDK;
    const __nv_bfloat16 *Kl = g_Klo + (size_t)bh * NL * NDK;
    const __nv_bfloat16 *Vh = g_VThi + (size_t)bh * NDK * NL;
    const __nv_bfloat16 *Vl = g_VTlo + (size_t)bh * NDK * NL;
    const uint32_t QHI = sb, QLO = sb + 16384, ST = sb + 32768;
    cp_tile(QHI, g_Qhi + ((size_t)bh * NL + q0) * NDK, 128, NDK, tid);
    cp_tile(QLO, g_Qlo + ((size_t)bh * NL + q0) * NDK, 128, NDK, tid);
    cpa_rows<64>(ST, Kh, NDK, tid);
    cpa_rows<64>(ST + 8192, Kl, NDK, tid);
    cpa_rows<64>(ST + 16384, Vh, NL, tid);
    cpa_rows<64>(ST + 24576, Vl, NL, tid);
    CPA_COMMIT();

    float oacc[8][4];
#pragma unroll
    for (int vt = 0; vt < 8; ++vt)
#pragma unroll
        for (int i = 0; i < 4; ++i) oacc[vt][i] = 0.f;

    for (int it = 0; it < 32; ++it) {
        if (it < 31) {
            uint32_t st = ST + (uint32_t)(((it + 1) & 1) * 32768);
            cpa_rows<64>(st, Kh + (size_t)(it + 1) * 64 * NDK, NDK, tid);
            cpa_rows<64>(st + 8192, Kl + (size_t)(it + 1) * 64 * NDK, NDK, tid);
            cpa_rows<64>(st + 16384, Vh + (size_t)(it + 1) * 64, NL, tid);
            cpa_rows<64>(st + 24576, Vl + (size_t)(it + 1) * 64, NL, tid);
            CPA_COMMIT();
            CPA_WAIT1();
        } else {
            CPA_WAIT0();
        }
        __syncthreads();
        const uint32_t SS = ST + (uint32_t)((it & 1) * 32768);
        float acc[8][4];
#pragma unroll
        for (int nt = 0; nt < 8; ++nt)
#pragma unroll
            for (int i = 0; i < 4; ++i) acc[nt][i] = 0.f;
        mma1_64(QHI, QLO, SS, SS + 8192, lane, wid * 16, acc);
#pragma unroll
        for (int kc2 = 0; kc2 < 4; ++kc2) {
            const int a = 2 * kc2, b = a + 1;
            float ea0 = fast_exp(acc[a][0] * 0.125f), ea1 = fast_exp(acc[a][1] * 0.125f);
            float ea2 = fast_exp(acc[a][2] * 0.125f), ea3 = fast_exp(acc[a][3] * 0.125f);
            float eb0 = fast_exp(acc[b][0] * 0.125f), eb1 = fast_exp(acc[b][1] * 0.125f);
            float eb2 = fast_exp(acc[b][2] * 0.125f), eb3 = fast_exp(acc[b][3] * 0.125f);
            uint32_t pah[4], pal[4];
            packsplit2(ea0, ea1, pah[0], pal[0]);
            packsplit2(ea2, ea3, pah[1], pal[1]);
            packsplit2(eb0, eb1, pah[2], pal[2]);
            packsplit2(eb2, eb3, pah[3], pal[3]);
            uint32_t vh0[8], vh1[8], vl0[8], vl1[8];
            ldB64(SS + 16384, lane, kc2, vh0, vh1);
            ldB64(SS + 24576, lane, kc2, vl0, vl1);
#pragma unroll
            for (int vt = 0; vt < 8; ++vt) {
                mma16816(oacc[vt], pah, vh0[vt], vh1[vt]);
                mma16816(oacc[vt], pah, vl0[vt], vl1[vt]);
                mma16816(oacc[vt], pal, vh0[vt], vh1[vt]);
            }
        }
        __syncthreads();
    }
    const int r = lane >> 2, c2 = (lane & 3) * 2;
    const size_t row0 = ((size_t)bb * NL + q0 + wid * 16 + r) * NDM + h * NDK;
    const size_t row1 = row0 + 8 * NDM;
#pragma unroll
    for (int vt = 0; vt < 8; ++vt) {
        int col = vt * 8 + c2;
        uint32_t hi, lo;
        packsplit2(oacc[vt][0], oacc[vt][1], hi, lo);
        *(uint32_t *)(g_Ohi + row0 + col) = hi;
        *(uint32_t *)(g_Olo + row0 + col) = lo;
        packsplit2(oacc[vt][2], oacc[vt][3], hi, lo);
        *(uint32_t *)(g_Ohi + row1 + col) = hi;
        *(uint32_t *)(g_Olo + row1 + col) = lo;
    }
}

// ---------------- kernel 5: out = cat_V @ Wo + bo (double-buffered) ----------------
__global__ void __launch_bounds__(256, 2) out_mm(const float *__restrict__ bo, float *__restrict__ out) {
    extern __shared__ char smem[];
    uint32_t sb = s2u(smem);
    const int tid = threadIdx.x, lane = tid & 31, wid = tid >> 5;
    const int wm = wid >> 1, wn = wid & 1;
    const int row0 = blockIdx.x * 128;
    const int n0 = blockIdx.y * 64;
    const __nv_bfloat16 *Ah = g_Ohi + (size_t)row0 * NDM;
    const __nv_bfloat16 *Al = g_Olo + (size_t)row0 * NDM;
    const __nv_bfloat16 *Bh = g_WoThi + (size_t)n0 * NDM;
    const __nv_bfloat16 *Bl = g_WoTlo + (size_t)n0 * NDM;

    cpa_rows<128>(sb + OFF_AHI, Ah, NDM, tid);
    cpa_rows<128>(sb + OFF_ALO, Al, NDM, tid);
    cpa_rows<64>(sb + OFF_BHI, Bh, NDM, tid);
    cpa_rows<64>(sb + OFF_BLO, Bl, NDM, tid);
    CPA_COMMIT();

    float acc[2][4][4];
    ACC_ZERO2(acc);
    for (int it = 0; it < 16; ++it) {
        if (it < 15) {
            uint32_t st = sb + (uint32_t)(((it + 1) & 1) * GBUF);
            cpa_rows<128>(st + OFF_AHI, Ah + (it + 1) * 64, NDM, tid);
            cpa_rows<128>(st + OFF_ALO, Al + (it + 1) * 64, NDM, tid);
            cpa_rows<64>(st + OFF_BHI, Bh + (it + 1) * 64, NDM, tid);
            cpa_rows<64>(st + OFF_BLO, Bl + (it + 1) * 64, NDM, tid);
            CPA_COMMIT();
            CPA_WAIT1();
        } else {
            CPA_WAIT0();
        }
        __syncthreads();
        mma_tile(sb + (uint32_t)((it & 1) * GBUF), lane, wm, wn, acc);
        __syncthreads();
    }
    const int trow = lane >> 2, tc = (lane & 3) * 2;
#pragma unroll
    for (int mt = 0; mt < 2; ++mt)
#pragma unroll
        for (int nt = 0; nt < 4; ++nt) {
            int col = n0 + wn * 32 + nt * 8 + tc;
            float2 b2 = *(const float2 *)(bo + col);
#pragma unroll
            for (int hh = 0; hh < 2; ++hh) {
                int row = row0 + wm * 32 + mt * 16 + trow + hh * 8;
                *(float2 *)(out + (size_t)row * NDM + col) =
                    make_float2(acc[mt][nt][2 * hh] + b2.x, acc[mt][nt][2 * hh + 1] + b2.y);
            }
        }
}

// ---------------- launch ----------------
extern "C" void kernel_launch(void *const *d_in, const int *in_sizes, int n_in,
                              void *d_out, int out_size) {
    const float *Q = (const float *)d_in[0];
    const float *K = (const float *)d_in[1];
    const float *V = (const float *)d_in[2];
    const float *Wq = (const float *)d_in[3];
    const float *bq = (const float *)d_in[4];
    const float *Wk = (const float *)d_in[5];
    const float *bk = (const float *)d_in[6];
    const float *Wv = (const float *)d_in[7];
    const float *bv = (const float *)d_in[8];
    const float *Wo = (const float *)d_in[9];
    const float *bo = (const float *)d_in[10];
    float *out = (float *)d_out;

    cudaFuncSetAttribute(proj_mm, cudaFuncAttributeMaxDynamicSharedMemorySize, PJ_SMEM);
    cudaFuncSetAttribute(phase1_mm, cudaFuncAttributeMaxDynamicSharedMemorySize, P1_SMEM);
    cudaFuncSetAttribute(attn_mm, cudaFuncAttributeMaxDynamicSharedMemorySize, P2_SMEM);
    cudaFuncSetAttribute(out_mm, cudaFuncAttributeMaxDynamicSharedMemorySize, PJ_SMEM);

    presplit<<<dim3(NM * NDM / (256 * 8), 3), 256>>>(Q, K, V);
    prep_wqkv<<<dim3(16, NH, 3), 256>>>(Wq, Wk, Wv);
    prep_wo<<<dim3(16, 16), 256>>>(Wo);
    zeroZ<<<64, 1024>>>();
    proj_mm<<<dim3(NH, NM / 128, 3), 256, PJ_SMEM>>>(bq, bk, bv);
    phase1_mm<<<dim3(NL / 128, NBH), 256, P1_SMEM>>>();
    vsplit_mm<<<dim3(NL / 64, NBH), 256>>>();
    attn_mm<<<dim3(NL / 128, NBH), 256, P2_SMEM>>>();
    out_mm<<<dim3(NM / 128, NDM / 64), 256, PJ_SMEM>>>(bo, out);
}

// round 6
// speedup vs baseline: 5.5829x; 1.3577x over previous
#include <cuda_runtime.h>
#include <cuda_fp16.h>
#include <cstdint>

#define NB 2
#define NL 2048
#define NDM 1024
#define NH 16
#define NDK 64
#define NBH 32
#define NM 4096

// ---------------- device scratch (alloc-free) ----------------
__device__ __align__(128) __half g_Xhi[3][(size_t)NM * NDM];  // pre-split inputs (A of proj)
__device__ __align__(128) __half g_Xlo[3][(size_t)NM * NDM];
__device__ __align__(128) __half g_Qhi[NBH * NL * NDK];       // Q projection, split (A of QK)
__device__ __align__(128) __half g_Qlo[NBH * NL * NDK];
__device__ __align__(128) __half g_K[NBH * NL * NDK];         // K projection, plain (B of QK)
__device__ __align__(128) float g_Vp[NBH * NL * NDK];
__device__ __align__(128) __half g_VT[NBH * NDK * NL];        // [bh][v][s], Zr-scaled, plain (B of PV)
__device__ __align__(128) float g_Z[NBH * NL];
__device__ __align__(128) __half g_Ohi[(size_t)NM * NDM];     // cat_V split (A of out)
__device__ __align__(128) __half g_Olo[(size_t)NM * NDM];
__device__ __align__(128) __half g_WT[3 * NH * NDK * NDM];    // [w][h][k][m], plain (B of proj)
__device__ __align__(128) __half g_WoT[NDM * NDM];            // [n][k], plain (B of out)

// ---------------- PTX helpers ----------------
__device__ __forceinline__ uint32_t s2u(const void *p) {
    uint32_t a;
    asm("{ .reg .u64 t; cvta.to.shared.u64 t, %1; cvt.u32.u64 %0, t; }" : "=r"(a) : "l"(p));
    return a;
}
__device__ __forceinline__ uint32_t swz(uint32_t o) { return o ^ ((o >> 3) & 0x70); }

__device__ __forceinline__ void ldsm4(uint32_t r[4], uint32_t addr) {
    asm volatile("ldmatrix.sync.aligned.m8n8.x4.shared.b16 {%0,%1,%2,%3}, [%4];"
                 : "=r"(r[0]), "=r"(r[1]), "=r"(r[2]), "=r"(r[3]) : "r"(addr));
}
__device__ __forceinline__ void mma16816(float d[4], const uint32_t a[4], uint32_t b0, uint32_t b1) {
    asm volatile("mma.sync.aligned.m16n8k16.row.col.f32.f16.f16.f32 "
                 "{%0,%1,%2,%3}, {%4,%5,%6,%7}, {%8,%9}, {%0,%1,%2,%3};"
                 : "+f"(d[0]), "+f"(d[1]), "+f"(d[2]), "+f"(d[3])
                 : "r"(a[0]), "r"(a[1]), "r"(a[2]), "r"(a[3]), "r"(b0), "r"(b1));
}
#define CPA_COMMIT() asm volatile("cp.async.commit_group;")
#define CPA_WAIT3() asm volatile("cp.async.wait_group 3;")
#define CPA_WAIT1() asm volatile("cp.async.wait_group 1;")
#define CPA_WAIT0() asm volatile("cp.async.wait_group 0;")

// ---------------- math ----------------
__device__ __forceinline__ float fast_exp(float x) {
    float t = x * 1.4426950408889634f;
    t = fmaxf(t, -126.0f);
    float r = t + 12582912.0f;
    int i = __float_as_int(r);
    float f = t - (r - 12582912.0f);
    float p = 1.33335581e-3f;
    p = fmaf(p, f, 9.61812911e-3f);
    p = fmaf(p, f, 5.55041087e-2f);
    p = fmaf(p, f, 2.40226507e-1f);
    p = fmaf(p, f, 6.93147180e-1f);
    p = fmaf(p, f, 1.0f);
    return __int_as_float(__float_as_int(p) + (i << 23));
}
__device__ __forceinline__ uint32_t packh2(float x0, float x1) {
    __half2 h = __floats2half2_rn(x0, x1);
    return *(uint32_t *)&h;
}
__device__ __forceinline__ void packsplit2(float x0, float x1, uint32_t &hi, uint32_t &lo) {
    __half2 h = __floats2half2_rn(x0, x1);
    float2 hf = __half22float2(h);
    __half2 l = __floats2half2_rn(x0 - hf.x, x1 - hf.y);
    hi = *(uint32_t *)&h;
    lo = *(uint32_t *)&l;
}

// ---------------- tile loaders ----------------
__device__ __forceinline__ void cp_tile(uint32_t dst, const __half *__restrict__ src,
                                        int rows, size_t ld, int tid) {
    for (int s = tid; s < rows * 8; s += 256) {
        int r = s >> 3, c8 = (s & 7) << 3;
        uint4 v = *(const uint4 *)(src + (size_t)r * ld + c8);
        asm volatile("st.shared.v4.b32 [%0], {%1,%2,%3,%4};"
                     ::"r"(dst + swz((uint32_t)(r * 128 + c8 * 2))), "r"(v.x), "r"(v.y), "r"(v.z), "r"(v.w));
    }
}
template <int ROWS>
__device__ __forceinline__ void cpa_rows(uint32_t dst, const __half *__restrict__ src,
                                         size_t ld, int tid) {
#pragma unroll
    for (int s = tid; s < ROWS * 8; s += 256) {
        int r = s >> 3, c8 = (s & 7) << 3;
        asm volatile("cp.async.ca.shared.global [%0], [%1], 16;"
                     ::"r"(dst + swz((uint32_t)(r * 128 + c8 * 2))), "l"(src + (size_t)r * ld + c8));
    }
}

// ---------------- fragment loads ----------------
__device__ __forceinline__ void ldA16(uint32_t tb, int lane, int qb, int kc, uint32_t a[4]) {
    int g = lane >> 3, l7 = lane & 7;
    uint32_t row = (uint32_t)(qb + ((g & 1) << 3) + l7);
    uint32_t kb = ((uint32_t)(((g >> 1) << 4) + kc * 32)) ^ ((uint32_t)l7 << 4);
    ldsm4(a, tb + row * 128 + kb);
}
__device__ __forceinline__ void ldB64(uint32_t tb, int lane, int kc, uint32_t b0[8], uint32_t b1[8]) {
    int g = lane >> 3, l7 = lane & 7;
    uint32_t xr = (uint32_t)l7 << 4;
    uint32_t r0 = tb + (uint32_t)(g * 8 + l7) * 128;
    uint32_t k0 = ((uint32_t)(kc * 32)) ^ xr;
    uint32_t k1 = ((uint32_t)(kc * 32 + 16)) ^ xr;
    ldsm4(b0, r0 + k0);
    ldsm4(b1, r0 + k1);
    ldsm4(b0 + 4, r0 + 4096 + k0);
    ldsm4(b1 + 4, r0 + 4096 + k1);
}
// 16q x 64s, A split (2 passes), B plain
__device__ __forceinline__ void mma1_64(uint32_t qhi, uint32_t qlo, uint32_t kb,
                                        int lane, int qb, float acc[8][4]) {
#pragma unroll
    for (int kc = 0; kc < 4; ++kc) {
        uint32_t ah[4], al[4];
        ldA16(qhi, lane, qb, kc, ah);
        ldA16(qlo, lane, qb, kc, al);
        uint32_t b0[8], b1[8];
        ldB64(kb, lane, kc, b0, b1);
#pragma unroll
        for (int nt = 0; nt < 8; ++nt) {
            mma16816(acc[nt], ah, b0[nt], b1[nt]);
            mma16816(acc[nt], al, b0[nt], b1[nt]);
        }
    }
}

// ---------------- 8-warp 128x64 block GEMM core ----------------
#define OFF_AHI 0
#define OFF_ALO 16384
#define OFF_B 32768
#define GBUF 40960
__device__ __forceinline__ void mma_tile(uint32_t sb, int lane, int wm, int wn, float acc[2][4][4]) {
    const uint32_t xr = (uint32_t)(lane & 7) << 4;
    const int g = lane >> 3;
    const int arow = ((g & 1) << 3) + (lane & 7);
    const uint32_t akh = (uint32_t)((g & 2) << 3);
    const uint32_t aA = (uint32_t)(wm * 32 + arow) * 128;
    const uint32_t aAhi = sb + OFF_AHI + aA, aAlo = sb + OFF_ALO + aA;
    const uint32_t aB = sb + OFF_B + (uint32_t)(wn * 32 + g * 8 + (lane & 7)) * 128;
#pragma unroll
    for (int kk = 0; kk < 4; ++kk) {
        const uint32_t ka = ((uint32_t)(kk * 32) + akh) ^ xr;
        const uint32_t kb0 = ((uint32_t)(kk * 32)) ^ xr;
        const uint32_t kb1 = ((uint32_t)(kk * 32 + 16)) ^ xr;
        uint32_t ah0[4], ah1[4], al0[4], al1[4];
        ldsm4(ah0, aAhi + ka);
        ldsm4(ah1, aAhi + 2048 + ka);
        ldsm4(al0, aAlo + ka);
        ldsm4(al1, aAlo + 2048 + ka);
        uint32_t b0[4], b1[4];
        ldsm4(b0, aB + kb0);
        ldsm4(b1, aB + kb1);
#pragma unroll
        for (int nt = 0; nt < 4; ++nt) {
            mma16816(acc[0][nt], ah0, b0[nt], b1[nt]);
            mma16816(acc[1][nt], ah1, b0[nt], b1[nt]);
            mma16816(acc[0][nt], al0, b0[nt], b1[nt]);
            mma16816(acc[1][nt], al1, b0[nt], b1[nt]);
        }
    }
}
#define ACC_ZERO2(acc)                                                   \
    do {                                                                 \
        _Pragma("unroll") for (int _m = 0; _m < 2; ++_m)                 \
            _Pragma("unroll") for (int _n = 0; _n < 4; ++_n)             \
                _Pragma("unroll") for (int _i = 0; _i < 4; ++_i) acc[_m][_n][_i] = 0.f; \
    } while (0)

// ---------------- prep kernels ----------------
__global__ void __launch_bounds__(256) presplit(const float *__restrict__ Q,
                                                const float *__restrict__ K,
                                                const float *__restrict__ V) {
    const int z = blockIdx.y;
    const float *X = (z == 0) ? Q : (z == 1) ? K : V;
    size_t i8 = ((size_t)blockIdx.x * 256 + threadIdx.x) * 8;
    float4 a = *(const float4 *)(X + i8);
    float4 b = *(const float4 *)(X + i8 + 4);
    uint32_t h[4], l[4];
    packsplit2(a.x, a.y, h[0], l[0]);
    packsplit2(a.z, a.w, h[1], l[1]);
    packsplit2(b.x, b.y, h[2], l[2]);
    packsplit2(b.z, b.w, h[3], l[3]);
    *(uint4 *)(&g_Xhi[z][i8]) = make_uint4(h[0], h[1], h[2], h[3]);
    *(uint4 *)(&g_Xlo[z][i8]) = make_uint4(l[0], l[1], l[2], l[3]);
}
__global__ void __launch_bounds__(256) prep_wqkv(const float *__restrict__ Wq,
                                                 const float *__restrict__ Wk,
                                                 const float *__restrict__ Wv) {
    __shared__ float ts[64][65];
    const int tid = threadIdx.x;
    const int mc = blockIdx.x, h = blockIdx.y, w = blockIdx.z;
    const float *W = (w == 0) ? Wq : (w == 1) ? Wk : Wv;
    const float *Wb = W + ((size_t)h * NDM + mc * 64) * NDK;
#pragma unroll
    for (int i = 0; i < 4; ++i) {
        int idx = tid + i * 256;
        int r = idx >> 4, c4 = (idx & 15) * 4;
        float4 v = *(const float4 *)(Wb + (size_t)r * NDK + c4);
        ts[r][c4] = v.x; ts[r][c4 + 1] = v.y; ts[r][c4 + 2] = v.z; ts[r][c4 + 3] = v.w;
    }
    __syncthreads();
    __half *Th = g_WT + (size_t)(w * NH + h) * NDK * NDM + mc * 64;
#pragma unroll
    for (int i = 0; i < 8; ++i) {
        int idx = tid + i * 256;
        int k = idx >> 5, mp = (idx & 31) * 2;
        *(uint32_t *)(Th + (size_t)k * NDM + mp) = packh2(ts[mp][k], ts[mp + 1][k]);
    }
}
__global__ void __launch_bounds__(256) prep_wo(const float *__restrict__ Wo) {
    __shared__ float ts[64][65];
    const int tid = threadIdx.x;
    const int nc = blockIdx.x, kc = blockIdx.y;
    const float *Wb = Wo + (size_t)kc * 64 * NDM + nc * 64;
#pragma unroll
    for (int i = 0; i < 4; ++i) {
        int idx = tid + i * 256;
        int r = idx >> 4, c4 = (idx & 15) * 4;
        float4 v = *(const float4 *)(Wb + (size_t)r * NDM + c4);
        ts[r][c4] = v.x; ts[r][c4 + 1] = v.y; ts[r][c4 + 2] = v.z; ts[r][c4 + 3] = v.w;
    }
    __syncthreads();
    __half *Th = g_WoT + (size_t)nc * 64 * NDM + kc * 64;
#pragma unroll
    for (int i = 0; i < 8; ++i) {
        int idx = tid + i * 256;
        int n = idx >> 5, kp = (idx & 31) * 2;
        *(uint32_t *)(Th + (size_t)n * NDM + kp) = packh2(ts[kp][n], ts[kp + 1][n]);
    }
}
__global__ void zeroZ() { g_Z[blockIdx.x * 1024 + threadIdx.x] = 0.0f; }

// ---------------- kernel 1: projections (double-buffered) ----------------
#define PJ_SMEM (2 * GBUF)
__global__ void __launch_bounds__(256, 2) proj_mm(const float *__restrict__ bq,
                                                  const float *__restrict__ bk,
                                                  const float *__restrict__ bv) {
    extern __shared__ char smem[];
    uint32_t sb = s2u(smem);
    const int tid = threadIdx.x, lane = tid & 31, wid = tid >> 5;
    const int wm = wid >> 1, wn = wid & 1;
    const int h = blockIdx.x;
    const int row0 = blockIdx.y * 128;
    const int wz = blockIdx.z;
    const float *bias = (wz == 0) ? bq : (wz == 1) ? bk : bv;
    const __half *Xh = g_Xhi[wz] + (size_t)row0 * NDM;
    const __half *Xl = g_Xlo[wz] + (size_t)row0 * NDM;
    const __half *WT = g_WT + (size_t)(wz * NH + h) * NDK * NDM;

    cpa_rows<128>(sb + OFF_AHI, Xh, NDM, tid);
    cpa_rows<128>(sb + OFF_ALO, Xl, NDM, tid);
    cpa_rows<64>(sb + OFF_B, WT, NDM, tid);
    CPA_COMMIT();

    float acc[2][4][4];
    ACC_ZERO2(acc);
    for (int it = 0; it < 16; ++it) {
        if (it < 15) {
            uint32_t st = sb + (uint32_t)(((it + 1) & 1) * GBUF);
            cpa_rows<128>(st + OFF_AHI, Xh + (it + 1) * 64, NDM, tid);
            cpa_rows<128>(st + OFF_ALO, Xl + (it + 1) * 64, NDM, tid);
            cpa_rows<64>(st + OFF_B, WT + (it + 1) * 64, NDM, tid);
            CPA_COMMIT();
            CPA_WAIT1();
        } else {
            CPA_WAIT0();
        }
        __syncthreads();
        mma_tile(sb + (uint32_t)((it & 1) * GBUF), lane, wm, wn, acc);
        __syncthreads();
    }
    const int trow = lane >> 2, tc = (lane & 3) * 2;
#pragma unroll
    for (int mt = 0; mt < 2; ++mt)
#pragma unroll
        for (int nt = 0; nt < 4; ++nt) {
            int col = wn * 32 + nt * 8 + tc;
            float2 b2 = *(const float2 *)(bias + h * NDK + col);
#pragma unroll
            for (int hh = 0; hh < 2; ++hh) {
                int grow = row0 + wm * 32 + mt * 16 + trow + hh * 8;
                int bb = grow >> 11, l = grow & (NL - 1);
                size_t off = ((size_t)(bb * NH + h) * NL + l) * NDK + col;
                float x0 = acc[mt][nt][2 * hh] + b2.x, x1 = acc[mt][nt][2 * hh + 1] + b2.y;
                if (wz == 2) {
                    *(float2 *)(g_Vp + off) = make_float2(x0, x1);
                } else if (wz == 1) {
                    *(uint32_t *)(g_K + off) = packh2(x0, x1);
                } else {
                    uint32_t hi, lo;
                    packsplit2(x0, x1, hi, lo);
                    *(uint32_t *)(g_Qhi + off) = hi;
                    *(uint32_t *)(g_Qlo + off) = lo;
                }
            }
        }
}

// ---------------- kernel 2 (phase 1): column sums of exp(S), 4-stage pipeline ----------------
#define P1_SMEM 65536
__global__ void __launch_bounds__(256, 2) phase1_mm() {
    extern __shared__ char smem[];
    uint32_t sb = s2u(smem);
    const int tid = threadIdx.x, lane = tid & 31, wid = tid >> 5;
    const int q0 = blockIdx.x * 128, bh = blockIdx.y;
    const __half *Kp = g_K + (size_t)bh * NL * NDK;
    const uint32_t QHI = sb, QLO = sb + 16384, KST = sb + 32768;
    cp_tile(QHI, g_Qhi + ((size_t)bh * NL + q0) * NDK, 128, NDK, tid);
    cp_tile(QLO, g_Qlo + ((size_t)bh * NL + q0) * NDK, 128, NDK, tid);
#pragma unroll
    for (int p = 0; p < 3; ++p) {
        cpa_rows<64>(KST + (uint32_t)(p * 8192), Kp + (size_t)p * 64 * NDK, NDK, tid);
        CPA_COMMIT();
    }
    float *Zp = g_Z + (size_t)bh * NL;
    for (int it = 0; it < 32; ++it) {
        if (it + 3 < 32)
            cpa_rows<64>(KST + (uint32_t)(((it + 3) & 3) * 8192), Kp + (size_t)(it + 3) * 64 * NDK, NDK, tid);
        CPA_COMMIT();
        CPA_WAIT3();
        __syncthreads();
        float acc[8][4];
#pragma unroll
        for (int nt = 0; nt < 8; ++nt)
#pragma unroll
            for (int i = 0; i < 4; ++i) acc[nt][i] = 0.f;
        mma1_64(QHI, QLO, KST + (uint32_t)((it & 3) * 8192), lane, wid * 16, acc);
        float *zcol = Zp + it * 64;
#pragma unroll
        for (int nt = 0; nt < 8; ++nt) {
            float e0 = fast_exp(acc[nt][0] * 0.125f);
            float e1 = fast_exp(acc[nt][1] * 0.125f);
            float e2 = fast_exp(acc[nt][2] * 0.125f);
            float e3 = fast_exp(acc[nt][3] * 0.125f);
            float c0 = e0 + e2, c1 = e1 + e3;
#pragma unroll
            for (int o = 4; o < 32; o <<= 1) {
                c0 += __shfl_xor_sync(0xffffffffu, c0, o);
                c1 += __shfl_xor_sync(0xffffffffu, c1, o);
            }
            if (lane < 4) {
                atomicAdd(zcol + nt * 8 + lane * 2, c0);
                atomicAdd(zcol + nt * 8 + lane * 2 + 1, c1);
            }
        }
        __syncthreads();
    }
}

// ---------------- kernel 3: V' = (V * 1/Z) transposed, plain fp16 ----------------
__global__ void __launch_bounds__(256) vsplit_mm() {
    __shared__ float ts[64][65];
    __shared__ float rz[64];
    const int tid = threadIdx.x;
    const int s0 = blockIdx.x * 64, bh = blockIdx.y;
    const float *Vb = g_Vp + ((size_t)bh * NL + s0) * NDK;
#pragma unroll
    for (int i = 0; i < 4; ++i) {
        int idx = tid + i * 256;
        int r = idx >> 4, c4 = (idx & 15) * 4;
        float4 v = *(const float4 *)(Vb + (size_t)r * NDK + c4);
        ts[r][c4] = v.x; ts[r][c4 + 1] = v.y; ts[r][c4 + 2] = v.z; ts[r][c4 + 3] = v.w;
    }
    if (tid < 64) rz[tid] = 1.0f / g_Z[(size_t)bh * NL + s0 + tid];
    __syncthreads();
    __half *Oh = g_VT + (size_t)bh * NDK * NL + s0;
#pragma unroll
    for (int i = 0; i < 8; ++i) {
        int idx = tid + i * 256;
        int v = idx >> 5, sp = (idx & 31) * 2;
        *(uint32_t *)(Oh + (size_t)v * NL + sp) = packh2(ts[sp][v] * rz[sp], ts[sp + 1][v] * rz[sp + 1]);
    }
}

// ---------------- kernel 4 (phase 2): O = exp(S)·V' fused, 4-stage pipeline ----------------
#define P2_SMEM 98304
__global__ void __launch_bounds__(256, 2) attn_mm() {
    extern __shared__ char smem[];
    uint32_t sb = s2u(smem);
    const int tid = threadIdx.x, lane = tid & 31, wid = tid >> 5;
    const int q0 = blockIdx.x * 128, bh = blockIdx.y;
    const int bb = bh >> 4, h = bh & 15;
    const __half *Kp = g_K + (size_t)bh * NL * NDK;
    const __half *Vt = g_VT + (size_t)bh * NDK * NL;
    const uint32_t QHI = sb, QLO = sb + 16384, ST = sb + 32768;  // 4 stages x (8KB K + 8KB V)
    cp_tile(QHI, g_Qhi + ((size_t)bh * NL + q0) * NDK, 128, NDK, tid);
    cp_tile(QLO, g_Qlo + ((size_t)bh * NL + q0) * NDK, 128, NDK, tid);
#pragma unroll
    for (int p = 0; p < 3; ++p) {
        uint32_t st = ST + (uint32_t)(p * 16384);
        cpa_rows<64>(st, Kp + (size_t)p * 64 * NDK, NDK, tid);
        cpa_rows<64>(st + 8192, Vt + (size_t)p * 64, NL, tid);
        CPA_COMMIT();
    }

    float oacc[8][4];
#pragma unroll
    for (int vt = 0; vt < 8; ++vt)
#pragma unroll
        for (int i = 0; i < 4; ++i) oacc[vt][i] = 0.f;

    for (int it = 0; it < 32; ++it) {
        if (it + 3 < 32) {
            uint32_t st = ST + (uint32_t)(((it + 3) & 3) * 16384);
            cpa_rows<64>(st, Kp + (size_t)(it + 3) * 64 * NDK, NDK, tid);
            cpa_rows<64>(st + 8192, Vt + (size_t)(it + 3) * 64, NL, tid);
        }
        CPA_COMMIT();
        CPA_WAIT3();
        __syncthreads();
        const uint32_t SS = ST + (uint32_t)((it & 3) * 16384);
        float acc[8][4];
#pragma unroll
        for (int nt = 0; nt < 8; ++nt)
#pragma unroll
            for (int i = 0; i < 4; ++i) acc[nt][i] = 0.f;
        mma1_64(QHI, QLO, SS, lane, wid * 16, acc);
#pragma unroll
        for (int kc2 = 0; kc2 < 4; ++kc2) {
            const int a = 2 * kc2, b = a + 1;
            float ea0 = fast_exp(acc[a][0] * 0.125f), ea1 = fast_exp(acc[a][1] * 0.125f);
            float ea2 = fast_exp(acc[a][2] * 0.125f), ea3 = fast_exp(acc[a][3] * 0.125f);
            float eb0 = fast_exp(acc[b][0] * 0.125f), eb1 = fast_exp(acc[b][1] * 0.125f);
            float eb2 = fast_exp(acc[b][2] * 0.125f), eb3 = fast_exp(acc[b][3] * 0.125f);
            uint32_t pah[4], pal[4];
            packsplit2(ea0, ea1, pah[0], pal[0]);
            packsplit2(ea2, ea3, pah[1], pal[1]);
            packsplit2(eb0, eb1, pah[2], pal[2]);
            packsplit2(eb2, eb3, pah[3], pal[3]);
            uint32_t v0[8], v1[8];
            ldB64(SS + 8192, lane, kc2, v0, v1);
#pragma unroll
            for (int vt = 0; vt < 8; ++vt) {
                mma16816(oacc[vt], pah, v0[vt], v1[vt]);
                mma16816(oacc[vt], pal, v0[vt], v1[vt]);
            }
        }
        __syncthreads();
    }
    const int r = lane >> 2, c2 = (lane & 3) * 2;
    const size_t row0 = ((size_t)bb * NL + q0 + wid * 16 + r) * NDM + h * NDK;
    const size_t row1 = row0 + 8 * NDM;
#pragma unroll
    for (int vt = 0; vt < 8; ++vt) {
        int col = vt * 8 + c2;
        uint32_t hi, lo;
        packsplit2(oacc[vt][0], oacc[vt][1], hi, lo);
        *(uint32_t *)(g_Ohi + row0 + col) = hi;
        *(uint32_t *)(g_Olo + row0 + col) = lo;
        packsplit2(oacc[vt][2], oacc[vt][3], hi, lo);
        *(uint32_t *)(g_Ohi + row1 + col) = hi;
        *(uint32_t *)(g_Olo + row1 + col) = lo;
    }
}

// ---------------- kernel 5: out = cat_V @ Wo + bo (double-buffered) ----------------
__global__ void __launch_bounds__(256, 2) out_mm(const float *__restrict__ bo, float *__restrict__ out) {
    extern __shared__ char smem[];
    uint32_t sb = s2u(smem);
    const int tid = threadIdx.x, lane = tid & 31, wid = tid >> 5;
    const int wm = wid >> 1, wn = wid & 1;
    const int row0 = blockIdx.x * 128;
    const int n0 = blockIdx.y * 64;
    const __half *Ah = g_Ohi + (size_t)row0 * NDM;
    const __half *Al = g_Olo + (size_t)row0 * NDM;
    const __half *Bh = g_WoT + (size_t)n0 * NDM;

    cpa_rows<128>(sb + OFF_AHI, Ah, NDM, tid);
    cpa_rows<128>(sb + OFF_ALO, Al, NDM, tid);
    cpa_rows<64>(sb + OFF_B, Bh, NDM, tid);
    CPA_COMMIT();

    float acc[2][4][4];
    ACC_ZERO2(acc);
    for (int it = 0; it < 16; ++it) {
        if (it < 15) {
            uint32_t st = sb + (uint32_t)(((it + 1) & 1) * GBUF);
            cpa_rows<128>(st + OFF_AHI, Ah + (it + 1) * 64, NDM, tid);
            cpa_rows<128>(st + OFF_ALO, Al + (it + 1) * 64, NDM, tid);
            cpa_rows<64>(st + OFF_B, Bh + (it + 1) * 64, NDM, tid);
            CPA_COMMIT();
            CPA_WAIT1();
        } else {
            CPA_WAIT0();
        }
        __syncthreads();
        mma_tile(sb + (uint32_t)((it & 1) * GBUF), lane, wm, wn, acc);
        __syncthreads();
    }
    const int trow = lane >> 2, tc = (lane & 3) * 2;
#pragma unroll
    for (int mt = 0; mt < 2; ++mt)
#pragma unroll
        for (int nt = 0; nt < 4; ++nt) {
            int col = n0 + wn * 32 + nt * 8 + tc;
            float2 b2 = *(const float2 *)(bo + col);
#pragma unroll
            for (int hh = 0; hh < 2; ++hh) {
                int row = row0 + wm * 32 + mt * 16 + trow + hh * 8;
                *(float2 *)(out + (size_t)row * NDM + col) =
                    make_float2(acc[mt][nt][2 * hh] + b2.x, acc[mt][nt][2 * hh + 1] + b2.y);
            }
        }
}

// ---------------- launch ----------------
extern "C" void kernel_launch(void *const *d_in, const int *in_sizes, int n_in,
                              void *d_out, int out_size) {
    const float *Q = (const float *)d_in[0];
    const float *K = (const float *)d_in[1];
    const float *V = (const float *)d_in[2];
    const float *Wq = (const float *)d_in[3];
    const float *bq = (const float *)d_in[4];
    const float *Wk = (const float *)d_in[5];
    const float *bk = (const float *)d_in[6];
    const float *Wv = (const float *)d_in[7];
    const float *bv = (const float *)d_in[8];
    const float *Wo = (const float *)d_in[9];
    const float *bo = (const float *)d_in[10];
    float *out = (float *)d_out;

    cudaFuncSetAttribute(proj_mm, cudaFuncAttributeMaxDynamicSharedMemorySize, PJ_SMEM);
    cudaFuncSetAttribute(phase1_mm, cudaFuncAttributeMaxDynamicSharedMemorySize, P1_SMEM);
    cudaFuncSetAttribute(attn_mm, cudaFuncAttributeMaxDynamicSharedMemorySize, P2_SMEM);
    cudaFuncSetAttribute(out_mm, cudaFuncAttributeMaxDynamicSharedMemorySize, PJ_SMEM);

    presplit<<<dim3(NM * NDM / (256 * 8), 3), 256>>>(Q, K, V);
    prep_wqkv<<<dim3(16, NH, 3), 256>>>(Wq, Wk, Wv);
    prep_wo<<<dim3(16, 16), 256>>>(Wo);
    zeroZ<<<64, 1024>>>();
    proj_mm<<<dim3(NH, NM / 128, 3), 256, PJ_SMEM>>>(bq, bk, bv);
    phase1_mm<<<dim3(NL / 128, NBH), 256, P1_SMEM>>>();
    vsplit_mm<<<dim3(NL / 64, NBH), 256>>>();
    attn_mm<<<dim3(NL / 128, NBH), 256, P2_SMEM>>>();
    out_mm<<<dim3(NM / 128, NDM / 64), 256, PJ_SMEM>>>(bo, out);
}

// round 7
// speedup vs baseline: 6.2618x; 1.1216x over previous
#include <cuda_runtime.h>
#include <cuda_fp16.h>
#include <cstdint>

#define NB 2
#define NL 2048
#define NDM 1024
#define NH 16
#define NDK 64
#define NBH 32
#define NM 4096

// ---------------- device scratch (alloc-free) ----------------
__device__ __align__(128) __half g_Xhi[3][(size_t)NM * NDM];  // pre-split inputs (A of proj)
__device__ __align__(128) __half g_Xlo[3][(size_t)NM * NDM];
__device__ __align__(128) __half g_Q[NBH * NL * NDK];         // Q projection, plain fp16 (A of QK)
__device__ __align__(128) __half g_K[NBH * NL * NDK];         // K projection, plain (B of QK)
__device__ __align__(128) float g_Vp[NBH * NL * NDK];
__device__ __align__(128) __half g_VT[NBH * NDK * NL];        // [bh][v][s], Zr-scaled (B of PV)
__device__ __align__(128) float g_Z[NBH * NL];
__device__ __align__(128) __half g_Ohi[(size_t)NM * NDM];     // cat_V split (A of out)
__device__ __align__(128) __half g_Olo[(size_t)NM * NDM];
__device__ __align__(128) __half g_WT[3 * NH * NDK * NDM];    // [w][h][n][m] (B of proj)
__device__ __align__(128) __half g_WoT[NDM * NDM];            // [n][k] (B of out)

// ---------------- PTX helpers ----------------
__device__ __forceinline__ uint32_t s2u(const void *p) {
    uint32_t a;
    asm("{ .reg .u64 t; cvta.to.shared.u64 t, %1; cvt.u32.u64 %0, t; }" : "=r"(a) : "l"(p));
    return a;
}
__device__ __forceinline__ uint32_t swz(uint32_t o) { return o ^ ((o >> 3) & 0x70); }

__device__ __forceinline__ void ldsm4(uint32_t r[4], uint32_t addr) {
    asm volatile("ldmatrix.sync.aligned.m8n8.x4.shared.b16 {%0,%1,%2,%3}, [%4];"
                 : "=r"(r[0]), "=r"(r[1]), "=r"(r[2]), "=r"(r[3]) : "r"(addr));
}
__device__ __forceinline__ void mma16816(float d[4], const uint32_t a[4], uint32_t b0, uint32_t b1) {
    asm volatile("mma.sync.aligned.m16n8k16.row.col.f32.f16.f16.f32 "
                 "{%0,%1,%2,%3}, {%4,%5,%6,%7}, {%8,%9}, {%0,%1,%2,%3};"
                 : "+f"(d[0]), "+f"(d[1]), "+f"(d[2]), "+f"(d[3])
                 : "r"(a[0]), "r"(a[1]), "r"(a[2]), "r"(a[3]), "r"(b0), "r"(b1));
}
#define CPA_COMMIT() asm volatile("cp.async.commit_group;")
#define CPA_WAIT3() asm volatile("cp.async.wait_group 3;")
#define CPA_WAIT1() asm volatile("cp.async.wait_group 1;")
#define CPA_WAIT0() asm volatile("cp.async.wait_group 0;")

// ---------------- math ----------------
__device__ __forceinline__ float fast_exp(float x) {
    float t = x * 1.4426950408889634f;
    t = fmaxf(t, -126.0f);
    float r = t + 12582912.0f;
    int i = __float_as_int(r);
    float f = t - (r - 12582912.0f);
    float p = 1.33335581e-3f;
    p = fmaf(p, f, 9.61812911e-3f);
    p = fmaf(p, f, 5.55041087e-2f);
    p = fmaf(p, f, 2.40226507e-1f);
    p = fmaf(p, f, 6.93147180e-1f);
    p = fmaf(p, f, 1.0f);
    return __int_as_float(__float_as_int(p) + (i << 23));
}
__device__ __forceinline__ uint32_t packh2(float x0, float x1) {
    __half2 h = __floats2half2_rn(x0, x1);
    return *(uint32_t *)&h;
}
__device__ __forceinline__ void packsplit2(float x0, float x1, uint32_t &hi, uint32_t &lo) {
    __half2 h = __floats2half2_rn(x0, x1);
    float2 hf = __half22float2(h);
    __half2 l = __floats2half2_rn(x0 - hf.x, x1 - hf.y);
    hi = *(uint32_t *)&h;
    lo = *(uint32_t *)&l;
}

// ---------------- tile loaders ----------------
__device__ __forceinline__ void cp_tile(uint32_t dst, const __half *__restrict__ src,
                                        int rows, size_t ld, int tid) {
    for (int s = tid; s < rows * 8; s += 256) {
        int r = s >> 3, c8 = (s & 7) << 3;
        uint4 v = *(const uint4 *)(src + (size_t)r * ld + c8);
        asm volatile("st.shared.v4.b32 [%0], {%1,%2,%3,%4};"
                     ::"r"(dst + swz((uint32_t)(r * 128 + c8 * 2))), "r"(v.x), "r"(v.y), "r"(v.z), "r"(v.w));
    }
}
template <int ROWS>
__device__ __forceinline__ void cpa_rows(uint32_t dst, const __half *__restrict__ src,
                                         size_t ld, int tid) {
#pragma unroll
    for (int s = tid; s < ROWS * 8; s += 256) {
        int r = s >> 3, c8 = (s & 7) << 3;
        asm volatile("cp.async.ca.shared.global [%0], [%1], 16;"
                     ::"r"(dst + swz((uint32_t)(r * 128 + c8 * 2))), "l"(src + (size_t)r * ld + c8));
    }
}

// ---------------- fragment loads ----------------
__device__ __forceinline__ void ldA16(uint32_t tb, int lane, int qb, int kc, uint32_t a[4]) {
    int g = lane >> 3, l7 = lane & 7;
    uint32_t row = (uint32_t)(qb + ((g & 1) << 3) + l7);
    uint32_t kb = ((uint32_t)(((g >> 1) << 4) + kc * 32)) ^ ((uint32_t)l7 << 4);
    ldsm4(a, tb + row * 128 + kb);
}
__device__ __forceinline__ void ldB64(uint32_t tb, int lane, int kc, uint32_t b0[8], uint32_t b1[8]) {
    int g = lane >> 3, l7 = lane & 7;
    uint32_t xr = (uint32_t)l7 << 4;
    uint32_t r0 = tb + (uint32_t)(g * 8 + l7) * 128;
    uint32_t k0 = ((uint32_t)(kc * 32)) ^ xr;
    uint32_t k1 = ((uint32_t)(kc * 32 + 16)) ^ xr;
    ldsm4(b0, r0 + k0);
    ldsm4(b1, r0 + k1);
    ldsm4(b0 + 4, r0 + 4096 + k0);
    ldsm4(b1 + 4, r0 + 4096 + k1);
}
// 16q x 64s, A plain, B plain (single pass)
__device__ __forceinline__ void mma1h_64(uint32_t qh, uint32_t kb, int lane, int qb, float acc[8][4]) {
#pragma unroll
    for (int kc = 0; kc < 4; ++kc) {
        uint32_t ah[4];
        ldA16(qh, lane, qb, kc, ah);
        uint32_t b0[8], b1[8];
        ldB64(kb, lane, kc, b0, b1);
#pragma unroll
        for (int nt = 0; nt < 8; ++nt) mma16816(acc[nt], ah, b0[nt], b1[nt]);
    }
}

// ---------------- 8-warp 128x128x64 block GEMM core (proj/out) ----------------
// warps: wm in 0..3 (rows of 32), wn in 0..1 (cols of 64); A split hi/lo, B plain.
#define OFF_AHI 0
#define OFF_ALO 16384
#define OFF_B 32768
#define GBUF 49152
__device__ __forceinline__ void mma_tile2(uint32_t sb, int lane, int wm, int wn, float acc[2][8][4]) {
    const uint32_t xr = (uint32_t)(lane & 7) << 4;
    const int g = lane >> 3;
    const int arow = ((g & 1) << 3) + (lane & 7);
    const uint32_t akh = (uint32_t)((g & 2) << 3);
    const uint32_t aA = (uint32_t)(wm * 32 + arow) * 128;
    const uint32_t aAhi = sb + OFF_AHI + aA, aAlo = sb + OFF_ALO + aA;
    const uint32_t bbase = sb + OFF_B + (uint32_t)(wn * 64) * 128;
#pragma unroll
    for (int kk = 0; kk < 4; ++kk) {
        const uint32_t ka = ((uint32_t)(kk * 32) + akh) ^ xr;
        uint32_t ah0[4], ah1[4], al0[4], al1[4];
        ldsm4(ah0, aAhi + ka);
        ldsm4(ah1, aAhi + 2048 + ka);
        ldsm4(al0, aAlo + ka);
        ldsm4(al1, aAlo + 2048 + ka);
        uint32_t b0[8], b1[8];
        ldB64(bbase, lane, kk, b0, b1);
#pragma unroll
        for (int nt = 0; nt < 8; ++nt) {
            mma16816(acc[0][nt], ah0, b0[nt], b1[nt]);
            mma16816(acc[1][nt], ah1, b0[nt], b1[nt]);
            mma16816(acc[0][nt], al0, b0[nt], b1[nt]);
            mma16816(acc[1][nt], al1, b0[nt], b1[nt]);
        }
    }
}
#define ACC_ZERO28(acc)                                                  \
    do {                                                                 \
        _Pragma("unroll") for (int _m = 0; _m < 2; ++_m)                 \
            _Pragma("unroll") for (int _n = 0; _n < 8; ++_n)             \
                _Pragma("unroll") for (int _i = 0; _i < 4; ++_i) acc[_m][_n][_i] = 0.f; \
    } while (0)

// ---------------- prep kernels ----------------
__global__ void __launch_bounds__(256) presplit(const float *__restrict__ Q,
                                                const float *__restrict__ K,
                                                const float *__restrict__ V) {
    const int z = blockIdx.y;
    const float *X = (z == 0) ? Q : (z == 1) ? K : V;
    size_t i8 = ((size_t)blockIdx.x * 256 + threadIdx.x) * 8;
    float4 a = *(const float4 *)(X + i8);
    float4 b = *(const float4 *)(X + i8 + 4);
    uint32_t h[4], l[4];
    packsplit2(a.x, a.y, h[0], l[0]);
    packsplit2(a.z, a.w, h[1], l[1]);
    packsplit2(b.x, b.y, h[2], l[2]);
    packsplit2(b.z, b.w, h[3], l[3]);
    *(uint4 *)(&g_Xhi[z][i8]) = make_uint4(h[0], h[1], h[2], h[3]);
    *(uint4 *)(&g_Xlo[z][i8]) = make_uint4(l[0], l[1], l[2], l[3]);
}
__global__ void __launch_bounds__(256) prep_wqkv(const float *__restrict__ Wq,
                                                 const float *__restrict__ Wk,
                                                 const float *__restrict__ Wv) {
    __shared__ float ts[64][65];
    const int tid = threadIdx.x;
    const int mc = blockIdx.x, h = blockIdx.y, w = blockIdx.z;
    const float *W = (w == 0) ? Wq : (w == 1) ? Wk : Wv;
    const float *Wb = W + ((size_t)h * NDM + mc * 64) * NDK;
#pragma unroll
    for (int i = 0; i < 4; ++i) {
        int idx = tid + i * 256;
        int r = idx >> 4, c4 = (idx & 15) * 4;
        float4 v = *(const float4 *)(Wb + (size_t)r * NDK + c4);
        ts[r][c4] = v.x; ts[r][c4 + 1] = v.y; ts[r][c4 + 2] = v.z; ts[r][c4 + 3] = v.w;
    }
    __syncthreads();
    __half *Th = g_WT + (size_t)(w * NH + h) * NDK * NDM + mc * 64;
#pragma unroll
    for (int i = 0; i < 8; ++i) {
        int idx = tid + i * 256;
        int k = idx >> 5, mp = (idx & 31) * 2;
        *(uint32_t *)(Th + (size_t)k * NDM + mp) = packh2(ts[mp][k], ts[mp + 1][k]);
    }
}
__global__ void __launch_bounds__(256) prep_wo(const float *__restrict__ Wo) {
    __shared__ float ts[64][65];
    const int tid = threadIdx.x;
    const int nc = blockIdx.x, kc = blockIdx.y;
    const float *Wb = Wo + (size_t)kc * 64 * NDM + nc * 64;
#pragma unroll
    for (int i = 0; i < 4; ++i) {
        int idx = tid + i * 256;
        int r = idx >> 4, c4 = (idx & 15) * 4;
        float4 v = *(const float4 *)(Wb + (size_t)r * NDM + c4);
        ts[r][c4] = v.x; ts[r][c4 + 1] = v.y; ts[r][c4 + 2] = v.z; ts[r][c4 + 3] = v.w;
    }
    __syncthreads();
    __half *Th = g_WoT + (size_t)nc * 64 * NDM + kc * 64;
#pragma unroll
    for (int i = 0; i < 8; ++i) {
        int idx = tid + i * 256;
        int n = idx >> 5, kp = (idx & 31) * 2;
        *(uint32_t *)(Th + (size_t)n * NDM + kp) = packh2(ts[kp][n], ts[kp + 1][n]);
    }
}
__global__ void zeroZ() { g_Z[blockIdx.x * 1024 + threadIdx.x] = 0.0f; }

// ---------------- kernel 1: projections (128x128 tile, double-buffered) ----------------
#define PJ_SMEM (2 * GBUF)
__global__ void __launch_bounds__(256, 2) proj_mm(const float *__restrict__ bq,
                                                  const float *__restrict__ bk,
                                                  const float *__restrict__ bv) {
    extern __shared__ char smem[];
    uint32_t sb = s2u(smem);
    const int tid = threadIdx.x, lane = tid & 31, wid = tid >> 5;
    const int wm = wid >> 1, wn = wid & 1;
    const int h0 = blockIdx.x * 2;  // two heads per block (N=128)
    const int row0 = blockIdx.y * 128;
    const int wz = blockIdx.z;
    const float *bias = (wz == 0) ? bq : (wz == 1) ? bk : bv;
    const __half *Xh = g_Xhi[wz] + (size_t)row0 * NDM;
    const __half *Xl = g_Xlo[wz] + (size_t)row0 * NDM;
    const __half *WT = g_WT + (size_t)(wz * NH + h0) * NDK * NDM;  // 128 contiguous n-rows

    cpa_rows<128>(sb + OFF_AHI, Xh, NDM, tid);
    cpa_rows<128>(sb + OFF_ALO, Xl, NDM, tid);
    cpa_rows<128>(sb + OFF_B, WT, NDM, tid);
    CPA_COMMIT();

    float acc[2][8][4];
    ACC_ZERO28(acc);
    for (int it = 0; it < 16; ++it) {
        if (it < 15) {
            uint32_t st = sb + (uint32_t)(((it + 1) & 1) * GBUF);
            cpa_rows<128>(st + OFF_AHI, Xh + (it + 1) * 64, NDM, tid);
            cpa_rows<128>(st + OFF_ALO, Xl + (it + 1) * 64, NDM, tid);
            cpa_rows<128>(st + OFF_B, WT + (it + 1) * 64, NDM, tid);
            CPA_COMMIT();
            CPA_WAIT1();
        } else {
            CPA_WAIT0();
        }
        __syncthreads();
        mma_tile2(sb + (uint32_t)((it & 1) * GBUF), lane, wm, wn, acc);
        __syncthreads();
    }
    const int trow = lane >> 2, tc = (lane & 3) * 2;
#pragma unroll
    for (int mt = 0; mt < 2; ++mt)
#pragma unroll
        for (int nt = 0; nt < 8; ++nt) {
            int col = wn * 64 + nt * 8 + tc;  // 0..127 across two heads
            int h = h0 + (col >> 6), c = col & 63;
            float2 b2 = *(const float2 *)(bias + h0 * NDK + col);
#pragma unroll
            for (int hh = 0; hh < 2; ++hh) {
                int grow = row0 + wm * 32 + mt * 16 + trow + hh * 8;
                int bb = grow >> 11, l = grow & (NL - 1);
                size_t off = ((size_t)(bb * NH + h) * NL + l) * NDK + c;
                float x0 = acc[mt][nt][2 * hh] + b2.x, x1 = acc[mt][nt][2 * hh + 1] + b2.y;
                if (wz == 2) {
                    *(float2 *)(g_Vp + off) = make_float2(x0, x1);
                } else if (wz == 1) {
                    *(uint32_t *)(g_K + off) = packh2(x0, x1);
                } else {
                    *(uint32_t *)(g_Q + off) = packh2(x0, x1);
                }
            }
        }
}

// ---------------- kernel 2 (phase 1): column sums of exp(S), 4-stage pipeline ----------------
#define P1_SMEM 49152
__global__ void __launch_bounds__(256, 2) phase1_mm() {
    extern __shared__ char smem[];
    uint32_t sb = s2u(smem);
    const int tid = threadIdx.x, lane = tid & 31, wid = tid >> 5;
    const int q0 = blockIdx.x * 128, bh = blockIdx.y;
    const __half *Kp = g_K + (size_t)bh * NL * NDK;
    const uint32_t QHI = sb, KST = sb + 16384;
    cp_tile(QHI, g_Q + ((size_t)bh * NL + q0) * NDK, 128, NDK, tid);
#pragma unroll
    for (int p = 0; p < 3; ++p) {
        cpa_rows<64>(KST + (uint32_t)(p * 8192), Kp + (size_t)p * 64 * NDK, NDK, tid);
        CPA_COMMIT();
    }
    float *Zp = g_Z + (size_t)bh * NL;
    for (int it = 0; it < 32; ++it) {
        if (it + 3 < 32)
            cpa_rows<64>(KST + (uint32_t)(((it + 3) & 3) * 8192), Kp + (size_t)(it + 3) * 64 * NDK, NDK, tid);
        CPA_COMMIT();
        CPA_WAIT3();
        __syncthreads();
        float acc[8][4];
#pragma unroll
        for (int nt = 0; nt < 8; ++nt)
#pragma unroll
            for (int i = 0; i < 4; ++i) acc[nt][i] = 0.f;
        mma1h_64(QHI, KST + (uint32_t)((it & 3) * 8192), lane, wid * 16, acc);
        float *zcol = Zp + it * 64;
#pragma unroll
        for (int nt = 0; nt < 8; ++nt) {
            float e0 = fast_exp(acc[nt][0] * 0.125f);
            float e1 = fast_exp(acc[nt][1] * 0.125f);
            float e2 = fast_exp(acc[nt][2] * 0.125f);
            float e3 = fast_exp(acc[nt][3] * 0.125f);
            float c0 = e0 + e2, c1 = e1 + e3;
#pragma unroll
            for (int o = 4; o < 32; o <<= 1) {
                c0 += __shfl_xor_sync(0xffffffffu, c0, o);
                c1 += __shfl_xor_sync(0xffffffffu, c1, o);
            }
            if (lane < 4) {
                atomicAdd(zcol + nt * 8 + lane * 2, c0);
                atomicAdd(zcol + nt * 8 + lane * 2 + 1, c1);
            }
        }
        __syncthreads();
    }
}

// ---------------- kernel 3: V' = (V * 1/Z) transposed, plain fp16 ----------------
__global__ void __launch_bounds__(256) vsplit_mm() {
    __shared__ float ts[64][65];
    __shared__ float rz[64];
    const int tid = threadIdx.x;
    const int s0 = blockIdx.x * 64, bh = blockIdx.y;
    const float *Vb = g_Vp + ((size_t)bh * NL + s0) * NDK;
#pragma unroll
    for (int i = 0; i < 4; ++i) {
        int idx = tid + i * 256;
        int r = idx >> 4, c4 = (idx & 15) * 4;
        float4 v = *(const float4 *)(Vb + (size_t)r * NDK + c4);
        ts[r][c4] = v.x; ts[r][c4 + 1] = v.y; ts[r][c4 + 2] = v.z; ts[r][c4 + 3] = v.w;
    }
    if (tid < 64) rz[tid] = 1.0f / g_Z[(size_t)bh * NL + s0 + tid];
    __syncthreads();
    __half *Oh = g_VT + (size_t)bh * NDK * NL + s0;
#pragma unroll
    for (int i = 0; i < 8; ++i) {
        int idx = tid + i * 256;
        int v = idx >> 5, sp = (idx & 31) * 2;
        *(uint32_t *)(Oh + (size_t)v * NL + sp) = packh2(ts[sp][v] * rz[sp], ts[sp + 1][v] * rz[sp + 1]);
    }
}

// ---------------- kernel 4 (phase 2): O = exp(S)·V' fused, 4-stage pipeline ----------------
#define P2_SMEM 81920
__global__ void __launch_bounds__(256, 2) attn_mm() {
    extern __shared__ char smem[];
    uint32_t sb = s2u(smem);
    const int tid = threadIdx.x, lane = tid & 31, wid = tid >> 5;
    const int q0 = blockIdx.x * 128, bh = blockIdx.y;
    const int bb = bh >> 4, h = bh & 15;
    const __half *Kp = g_K + (size_t)bh * NL * NDK;
    const __half *Vt = g_VT + (size_t)bh * NDK * NL;
    const uint32_t QHI = sb, ST = sb + 16384;  // 4 stages x (8KB K + 8KB V)
    cp_tile(QHI, g_Q + ((size_t)bh * NL + q0) * NDK, 128, NDK, tid);
#pragma unroll
    for (int p = 0; p < 3; ++p) {
        uint32_t st = ST + (uint32_t)(p * 16384);
        cpa_rows<64>(st, Kp + (size_t)p * 64 * NDK, NDK, tid);
        cpa_rows<64>(st + 8192, Vt + (size_t)p * 64, NL, tid);
        CPA_COMMIT();
    }

    float oacc[8][4];
#pragma unroll
    for (int vt = 0; vt < 8; ++vt)
#pragma unroll
        for (int i = 0; i < 4; ++i) oacc[vt][i] = 0.f;

    for (int it = 0; it < 32; ++it) {
        if (it + 3 < 32) {
            uint32_t st = ST + (uint32_t)(((it + 3) & 3) * 16384);
            cpa_rows<64>(st, Kp + (size_t)(it + 3) * 64 * NDK, NDK, tid);
            cpa_rows<64>(st + 8192, Vt + (size_t)(it + 3) * 64, NL, tid);
        }
        CPA_COMMIT();
        CPA_WAIT3();
        __syncthreads();
        const uint32_t SS = ST + (uint32_t)((it & 3) * 16384);
        float acc[8][4];
#pragma unroll
        for (int nt = 0; nt < 8; ++nt)
#pragma unroll
            for (int i = 0; i < 4; ++i) acc[nt][i] = 0.f;
        mma1h_64(QHI, SS, lane, wid * 16, acc);
#pragma unroll
        for (int kc2 = 0; kc2 < 4; ++kc2) {
            const int a = 2 * kc2, b = a + 1;
            float ea0 = fast_exp(acc[a][0] * 0.125f), ea1 = fast_exp(acc[a][1] * 0.125f);
            float ea2 = fast_exp(acc[a][2] * 0.125f), ea3 = fast_exp(acc[a][3] * 0.125f);
            float eb0 = fast_exp(acc[b][0] * 0.125f), eb1 = fast_exp(acc[b][1] * 0.125f);
            float eb2 = fast_exp(acc[b][2] * 0.125f), eb3 = fast_exp(acc[b][3] * 0.125f);
            uint32_t pah[4], pal[4];
            packsplit2(ea0, ea1, pah[0], pal[0]);
            packsplit2(ea2, ea3, pah[1], pal[1]);
            packsplit2(eb0, eb1, pah[2], pal[2]);
            packsplit2(eb2, eb3, pah[3], pal[3]);
            uint32_t v0[8], v1[8];
            ldB64(SS + 8192, lane, kc2, v0, v1);
#pragma unroll
            for (int vt = 0; vt < 8; ++vt) {
                mma16816(oacc[vt], pah, v0[vt], v1[vt]);
                mma16816(oacc[vt], pal, v0[vt], v1[vt]);
            }
        }
        __syncthreads();
    }
    const int r = lane >> 2, c2 = (lane & 3) * 2;
    const size_t row0 = ((size_t)bb * NL + q0 + wid * 16 + r) * NDM + h * NDK;
    const size_t row1 = row0 + 8 * NDM;
#pragma unroll
    for (int vt = 0; vt < 8; ++vt) {
        int col = vt * 8 + c2;
        uint32_t hi, lo;
        packsplit2(oacc[vt][0], oacc[vt][1], hi, lo);
        *(uint32_t *)(g_Ohi + row0 + col) = hi;
        *(uint32_t *)(g_Olo + row0 + col) = lo;
        packsplit2(oacc[vt][2], oacc[vt][3], hi, lo);
        *(uint32_t *)(g_Ohi + row1 + col) = hi;
        *(uint32_t *)(g_Olo + row1 + col) = lo;
    }
}

// ---------------- kernel 5: out = cat_V @ Wo + bo (128x128 tile, double-buffered) ----------------
__global__ void __launch_bounds__(256, 2) out_mm(const float *__restrict__ bo, float *__restrict__ out) {
    extern __shared__ char smem[];
    uint32_t sb = s2u(smem);
    const int tid = threadIdx.x, lane = tid & 31, wid = tid >> 5;
    const int wm = wid >> 1, wn = wid & 1;
    const int row0 = blockIdx.x * 128;
    const int n0 = blockIdx.y * 128;
    const __half *Ah = g_Ohi + (size_t)row0 * NDM;
    const __half *Al = g_Olo + (size_t)row0 * NDM;
    const __half *Bh = g_WoT + (size_t)n0 * NDM;

    cpa_rows<128>(sb + OFF_AHI, Ah, NDM, tid);
    cpa_rows<128>(sb + OFF_ALO, Al, NDM, tid);
    cpa_rows<128>(sb + OFF_B, Bh, NDM, tid);
    CPA_COMMIT();

    float acc[2][8][4];
    ACC_ZERO28(acc);
    for (int it = 0; it < 16; ++it) {
        if (it < 15) {
            uint32_t st = sb + (uint32_t)(((it + 1) & 1) * GBUF);
            cpa_rows<128>(st + OFF_AHI, Ah + (it + 1) * 64, NDM, tid);
            cpa_rows<128>(st + OFF_ALO, Al + (it + 1) * 64, NDM, tid);
            cpa_rows<128>(st + OFF_B, Bh + (it + 1) * 64, NDM, tid);
            CPA_COMMIT();
            CPA_WAIT1();
        } else {
            CPA_WAIT0();
        }
        __syncthreads();
        mma_tile2(sb + (uint32_t)((it & 1) * GBUF), lane, wm, wn, acc);
        __syncthreads();
    }
    const int trow = lane >> 2, tc = (lane & 3) * 2;
#pragma unroll
    for (int mt = 0; mt < 2; ++mt)
#pragma unroll
        for (int nt = 0; nt < 8; ++nt) {
            int col = n0 + wn * 64 + nt * 8 + tc;
            float2 b2 = *(const float2 *)(bo + col);
#pragma unroll
            for (int hh = 0; hh < 2; ++hh) {
                int row = row0 + wm * 32 + mt * 16 + trow + hh * 8;
                *(float2 *)(out + (size_t)row * NDM + col) =
                    make_float2(acc[mt][nt][2 * hh] + b2.x, acc[mt][nt][2 * hh + 1] + b2.y);
            }
        }
}

// ---------------- launch ----------------
extern "C" void kernel_launch(void *const *d_in, const int *in_sizes, int n_in,
                              void *d_out, int out_size) {
    const float *Q = (const float *)d_in[0];
    const float *K = (const float *)d_in[1];
    const float *V = (const float *)d_in[2];
    const float *Wq = (const float *)d_in[3];
    const float *bq = (const float *)d_in[4];
    const float *Wk = (const float *)d_in[5];
    const float *bk = (const float *)d_in[6];
    const float *Wv = (const float *)d_in[7];
    const float *bv = (const float *)d_in[8];
    const float *Wo = (const float *)d_in[9];
    const float *bo = (const float *)d_in[10];
    float *out = (float *)d_out;

    cudaFuncSetAttribute(proj_mm, cudaFuncAttributeMaxDynamicSharedMemorySize, PJ_SMEM);
    cudaFuncSetAttribute(phase1_mm, cudaFuncAttributeMaxDynamicSharedMemorySize, P1_SMEM);
    cudaFuncSetAttribute(attn_mm, cudaFuncAttributeMaxDynamicSharedMemorySize, P2_SMEM);
    cudaFuncSetAttribute(out_mm, cudaFuncAttributeMaxDynamicSharedMemorySize, PJ_SMEM);

    presplit<<<dim3(NM * NDM / (256 * 8), 3), 256>>>(Q, K, V);
    prep_wqkv<<<dim3(16, NH, 3), 256>>>(Wq, Wk, Wv);
    prep_wo<<<dim3(16, 16), 256>>>(Wo);
    zeroZ<<<64, 1024>>>();
    proj_mm<<<dim3(NH / 2, NM / 128, 3), 256, PJ_SMEM>>>(bq, bk, bv);
    phase1_mm<<<dim3(NL / 128, NBH), 256, P1_SMEM>>>();
    vsplit_mm<<<dim3(NL / 64, NBH), 256>>>();
    attn_mm<<<dim3(NL / 128, NBH), 256, P2_SMEM>>>();
    out_mm<<<dim3(NM / 128, NDM / 128), 256, PJ_SMEM>>>(bo, out);
}

// round 9
// speedup vs baseline: 8.3238x; 1.3293x over previous
#include <cuda_runtime.h>
#include <cuda_fp16.h>
#include <cstdint>

#define NB 2
#define NL 2048
#define NDM 1024
#define NH 16
#define NDK 64
#define NBH 32
#define NM 4096

// ---------------- device scratch (alloc-free) ----------------
__device__ __align__(128) __half g_X[3][(size_t)NM * NDM];  // fp16 inputs (A of proj)
__device__ __align__(128) __half g_Q[NBH * NL * NDK];       // Q projection (A of QK)
__device__ __align__(128) __half g_K[NBH * NL * NDK];       // K projection (B of QK)
__device__ __align__(128) float g_Vp[NBH * NL * NDK];
__device__ __align__(128) __half g_VT[NBH * NDK * NL];      // [bh][v][s], Zr-scaled (B of PV)
__device__ __align__(128) float g_Z[NBH * NL];
__device__ __align__(128) __half g_O[(size_t)NM * NDM];     // cat_V (A of out)
__device__ __align__(128) __half g_WT[3 * NH * NDK * NDM];  // [w][h][n][m] (B of proj)
__device__ __align__(128) __half g_WoT[NDM * NDM];          // [n][k] (B of out)

// ---------------- PTX helpers ----------------
__device__ __forceinline__ uint32_t s2u(const void *p) {
    uint32_t a;
    asm("{ .reg .u64 t; cvta.to.shared.u64 t, %1; cvt.u32.u64 %0, t; }" : "=r"(a) : "l"(p));
    return a;
}
__device__ __forceinline__ uint32_t swz(uint32_t o) { return o ^ ((o >> 3) & 0x70); }

__device__ __forceinline__ void ldsm4(uint32_t r[4], uint32_t addr) {
    asm volatile("ldmatrix.sync.aligned.m8n8.x4.shared.b16 {%0,%1,%2,%3}, [%4];"
                 : "=r"(r[0]), "=r"(r[1]), "=r"(r[2]), "=r"(r[3]) : "r"(addr));
}
__device__ __forceinline__ void mma16816(float d[4], const uint32_t a[4], uint32_t b0, uint32_t b1) {
    asm volatile("mma.sync.aligned.m16n8k16.row.col.f32.f16.f16.f32 "
                 "{%0,%1,%2,%3}, {%4,%5,%6,%7}, {%8,%9}, {%0,%1,%2,%3};"
                 : "+f"(d[0]), "+f"(d[1]), "+f"(d[2]), "+f"(d[3])
                 : "r"(a[0]), "r"(a[1]), "r"(a[2]), "r"(a[3]), "r"(b0), "r"(b1));
}
#define CPA_COMMIT() asm volatile("cp.async.commit_group;")
#define CPA_WAIT3() asm volatile("cp.async.wait_group 3;")
#define CPA_WAIT1() asm volatile("cp.async.wait_group 1;")
#define CPA_WAIT0() asm volatile("cp.async.wait_group 0;")

// ---------------- math ----------------
__device__ __forceinline__ float fast_exp(float x) {
    float t = x * 1.4426950408889634f;
    t = fmaxf(t, -126.0f);
    float r = t + 12582912.0f;
    int i = __float_as_int(r);
    float f = t - (r - 12582912.0f);
    float p = 1.33335581e-3f;
    p = fmaf(p, f, 9.61812911e-3f);
    p = fmaf(p, f, 5.55041087e-2f);
    p = fmaf(p, f, 2.40226507e-1f);
    p = fmaf(p, f, 6.93147180e-1f);
    p = fmaf(p, f, 1.0f);
    return __int_as_float(__float_as_int(p) + (i << 23));
}
__device__ __forceinline__ uint32_t packh2(float x0, float x1) {
    __half2 h = __floats2half2_rn(x0, x1);
    return *(uint32_t *)&h;
}

// ---------------- tile loaders ----------------
__device__ __forceinline__ void cp_tile(uint32_t dst, const __half *__restrict__ src,
                                        int rows, size_t ld, int tid) {
    for (int s = tid; s < rows * 8; s += 256) {
        int r = s >> 3, c8 = (s & 7) << 3;
        uint4 v = *(const uint4 *)(src + (size_t)r * ld + c8);
        asm volatile("st.shared.v4.b32 [%0], {%1,%2,%3,%4};"
                     ::"r"(dst + swz((uint32_t)(r * 128 + c8 * 2))), "r"(v.x), "r"(v.y), "r"(v.z), "r"(v.w));
    }
}
template <int ROWS>
__device__ __forceinline__ void cpa_rows(uint32_t dst, const __half *__restrict__ src,
                                         size_t ld, int tid) {
#pragma unroll
    for (int s = tid; s < ROWS * 8; s += 256) {
        int r = s >> 3, c8 = (s & 7) << 3;
        asm volatile("cp.async.ca.shared.global [%0], [%1], 16;"
                     ::"r"(dst + swz((uint32_t)(r * 128 + c8 * 2))), "l"(src + (size_t)r * ld + c8));
    }
}

// ---------------- fragment loads ----------------
__device__ __forceinline__ void ldA16(uint32_t tb, int lane, int qb, int kc, uint32_t a[4]) {
    int g = lane >> 3, l7 = lane & 7;
    uint32_t row = (uint32_t)(qb + ((g & 1) << 3) + l7);
    uint32_t kb = ((uint32_t)(((g >> 1) << 4) + kc * 32)) ^ ((uint32_t)l7 << 4);
    ldsm4(a, tb + row * 128 + kb);
}
__device__ __forceinline__ void ldB64(uint32_t tb, int lane, int kc, uint32_t b0[8], uint32_t b1[8]) {
    int g = lane >> 3, l7 = lane & 7;
    uint32_t xr = (uint32_t)l7 << 4;
    uint32_t r0 = tb + (uint32_t)(g * 8 + l7) * 128;
    uint32_t k0 = ((uint32_t)(kc * 32)) ^ xr;
    uint32_t k1 = ((uint32_t)(kc * 32 + 16)) ^ xr;
    ldsm4(b0, r0 + k0);
    ldsm4(b1, r0 + k1);
    ldsm4(b0 + 4, r0 + 4096 + k0);
    ldsm4(b1 + 4, r0 + 4096 + k1);
}
// 16q x 64s, single pass
__device__ __forceinline__ void mma1h_64(uint32_t qh, uint32_t kb, int lane, int qb, float acc[8][4]) {
#pragma unroll
    for (int kc = 0; kc < 4; ++kc) {
        uint32_t ah[4];
        ldA16(qh, lane, qb, kc, ah);
        uint32_t b0[8], b1[8];
        ldB64(kb, lane, kc, b0, b1);
#pragma unroll
        for (int nt = 0; nt < 8; ++nt) mma16816(acc[nt], ah, b0[nt], b1[nt]);
    }
}

// ---------------- 8-warp 128x128x64 block GEMM core (single-A) ----------------
#define OFF_A 0
#define OFF_B 16384
#define GBUF 32768
__device__ __forceinline__ void mma_tile_s(uint32_t sb, int lane, int wm, int wn, float acc[2][8][4]) {
    const uint32_t xr = (uint32_t)(lane & 7) << 4;
    const int g = lane >> 3;
    const int arow = ((g & 1) << 3) + (lane & 7);
    const uint32_t akh = (uint32_t)((g & 2) << 3);
    const uint32_t aA = sb + OFF_A + (uint32_t)(wm * 32 + arow) * 128;
    const uint32_t bbase = sb + OFF_B + (uint32_t)(wn * 64) * 128;
#pragma unroll
    for (int kk = 0; kk < 4; ++kk) {
        const uint32_t ka = ((uint32_t)(kk * 32) + akh) ^ xr;
        uint32_t ah0[4], ah1[4];
        ldsm4(ah0, aA + ka);
        ldsm4(ah1, aA + 2048 + ka);
        uint32_t b0[8], b1[8];
        ldB64(bbase, lane, kk, b0, b1);
#pragma unroll
        for (int nt = 0; nt < 8; ++nt) {
            mma16816(acc[0][nt], ah0, b0[nt], b1[nt]);
            mma16816(acc[1][nt], ah1, b0[nt], b1[nt]);
        }
    }
}
#define ACC_ZERO28(acc)                                                  \
    do {                                                                 \
        _Pragma("unroll") for (int _m = 0; _m < 2; ++_m)                 \
            _Pragma("unroll") for (int _n = 0; _n < 8; ++_n)             \
                _Pragma("unroll") for (int _i = 0; _i < 4; ++_i) acc[_m][_n][_i] = 0.f; \
    } while (0)

// ---------------- prep kernels ----------------
__global__ void __launch_bounds__(256) tofp16(const float *__restrict__ Q,
                                              const float *__restrict__ K,
                                              const float *__restrict__ V) {
    const int z = blockIdx.y;
    const float *X = (z == 0) ? Q : (z == 1) ? K : V;
    size_t i8 = ((size_t)blockIdx.x * 256 + threadIdx.x) * 8;
    float4 a = *(const float4 *)(X + i8);
    float4 b = *(const float4 *)(X + i8 + 4);
    *(uint4 *)(&g_X[z][i8]) = make_uint4(packh2(a.x, a.y), packh2(a.z, a.w),
                                         packh2(b.x, b.y), packh2(b.z, b.w));
}
__global__ void __launch_bounds__(256) prep_wqkv(const float *__restrict__ Wq,
                                                 const float *__restrict__ Wk,
                                                 const float *__restrict__ Wv) {
    __shared__ float ts[64][65];
    const int tid = threadIdx.x;
    const int mc = blockIdx.x, h = blockIdx.y, w = blockIdx.z;
    const float *W = (w == 0) ? Wq : (w == 1) ? Wk : Wv;
    const float *Wb = W + ((size_t)h * NDM + mc * 64) * NDK;
#pragma unroll
    for (int i = 0; i < 4; ++i) {
        int idx = tid + i * 256;
        int r = idx >> 4, c4 = (idx & 15) * 4;
        float4 v = *(const float4 *)(Wb + (size_t)r * NDK + c4);
        ts[r][c4] = v.x; ts[r][c4 + 1] = v.y; ts[r][c4 + 2] = v.z; ts[r][c4 + 3] = v.w;
    }
    __syncthreads();
    __half *Th = g_WT + (size_t)(w * NH + h) * NDK * NDM + mc * 64;
#pragma unroll
    for (int i = 0; i < 8; ++i) {
        int idx = tid + i * 256;
        int k = idx >> 5, mp = (idx & 31) * 2;
        *(uint32_t *)(Th + (size_t)k * NDM + mp) = packh2(ts[mp][k], ts[mp + 1][k]);
    }
}
__global__ void __launch_bounds__(256) prep_wo(const float *__restrict__ Wo) {
    __shared__ float ts[64][65];
    const int tid = threadIdx.x;
    const int nc = blockIdx.x, kc = blockIdx.y;
    const float *Wb = Wo + (size_t)kc * 64 * NDM + nc * 64;
#pragma unroll
    for (int i = 0; i < 4; ++i) {
        int idx = tid + i * 256;
        int r = idx >> 4, c4 = (idx & 15) * 4;
        float4 v = *(const float4 *)(Wb + (size_t)r * NDM + c4);
        ts[r][c4] = v.x; ts[r][c4 + 1] = v.y; ts[r][c4 + 2] = v.z; ts[r][c4 + 3] = v.w;
    }
    __syncthreads();
    __half *Th = g_WoT + (size_t)nc * 64 * NDM + kc * 64;
#pragma unroll
    for (int i = 0; i < 8; ++i) {
        int idx = tid + i * 256;
        int n = idx >> 5, kp = (idx & 31) * 2;
        *(uint32_t *)(Th + (size_t)n * NDM + kp) = packh2(ts[kp][n], ts[kp + 1][n]);
    }
}
__global__ void zeroZ() { g_Z[blockIdx.x * 1024 + threadIdx.x] = 0.0f; }

// ---------------- kernel 1: projections (128x128 tile, wait->sync->mma->sync) ----------------
#define PJ_SMEM (2 * GBUF)
__global__ void __launch_bounds__(256, 2) proj_mm(const float *__restrict__ bq,
                                                  const float *__restrict__ bk,
                                                  const float *__restrict__ bv) {
    extern __shared__ char smem[];
    uint32_t sb = s2u(smem);
    const int tid = threadIdx.x, lane = tid & 31, wid = tid >> 5;
    const int wm = wid >> 1, wn = wid & 1;
    const int h0 = blockIdx.x * 2;
    const int row0 = blockIdx.y * 128;
    const int wz = blockIdx.z;
    const float *bias = (wz == 0) ? bq : (wz == 1) ? bk : bv;
    const __half *Xp = g_X[wz] + (size_t)row0 * NDM;
    const __half *WT = g_WT + (size_t)(wz * NH + h0) * NDK * NDM;

    cpa_rows<128>(sb + OFF_A, Xp, NDM, tid);
    cpa_rows<128>(sb + OFF_B, WT, NDM, tid);
    CPA_COMMIT();

    float acc[2][8][4];
    ACC_ZERO28(acc);
    for (int it = 0; it < 16; ++it) {
        if (it < 15) {
            uint32_t st = sb + (uint32_t)(((it + 1) & 1) * GBUF);
            cpa_rows<128>(st + OFF_A, Xp + (it + 1) * 64, NDM, tid);
            cpa_rows<128>(st + OFF_B, WT + (it + 1) * 64, NDM, tid);
            CPA_COMMIT();
            CPA_WAIT1();
        } else {
            CPA_WAIT0();
        }
        __syncthreads();
        mma_tile_s(sb + (uint32_t)((it & 1) * GBUF), lane, wm, wn, acc);
        __syncthreads();
    }
    const int trow = lane >> 2, tc = (lane & 3) * 2;
#pragma unroll
    for (int mt = 0; mt < 2; ++mt)
#pragma unroll
        for (int nt = 0; nt < 8; ++nt) {
            int col = wn * 64 + nt * 8 + tc;
            int h = h0 + (col >> 6), c = col & 63;
            float2 b2 = *(const float2 *)(bias + h0 * NDK + col);
#pragma unroll
            for (int hh = 0; hh < 2; ++hh) {
                int grow = row0 + wm * 32 + mt * 16 + trow + hh * 8;
                int bb = grow >> 11, l = grow & (NL - 1);
                size_t off = ((size_t)(bb * NH + h) * NL + l) * NDK + c;
                float x0 = acc[mt][nt][2 * hh] + b2.x, x1 = acc[mt][nt][2 * hh + 1] + b2.y;
                if (wz == 2) {
                    *(float2 *)(g_Vp + off) = make_float2(x0, x1);
                } else if (wz == 1) {
                    *(uint32_t *)(g_K + off) = packh2(x0, x1);
                } else {
                    *(uint32_t *)(g_Q + off) = packh2(x0, x1);
                }
            }
        }
}

// ---------------- kernel 2 (phase 1): column sums of exp(S), 4-stage ----------------
#define P1_SMEM 49152
__global__ void __launch_bounds__(256, 2) phase1_mm() {
    extern __shared__ char smem[];
    uint32_t sb = s2u(smem);
    const int tid = threadIdx.x, lane = tid & 31, wid = tid >> 5;
    const int q0 = blockIdx.x * 128, bh = blockIdx.y;
    const __half *Kp = g_K + (size_t)bh * NL * NDK;
    const uint32_t QT = sb, KST = sb + 16384;
    cp_tile(QT, g_Q + ((size_t)bh * NL + q0) * NDK, 128, NDK, tid);
#pragma unroll
    for (int p = 0; p < 3; ++p) {
        cpa_rows<64>(KST + (uint32_t)(p * 8192), Kp + (size_t)p * 64 * NDK, NDK, tid);
        CPA_COMMIT();
    }
    float *Zp = g_Z + (size_t)bh * NL;
    for (int it = 0; it < 32; ++it) {
        if (it + 3 < 32)
            cpa_rows<64>(KST + (uint32_t)(((it + 3) & 3) * 8192), Kp + (size_t)(it + 3) * 64 * NDK, NDK, tid);
        CPA_COMMIT();
        CPA_WAIT3();
        __syncthreads();
        float acc[8][4];
#pragma unroll
        for (int nt = 0; nt < 8; ++nt)
#pragma unroll
            for (int i = 0; i < 4; ++i) acc[nt][i] = 0.f;
        mma1h_64(QT, KST + (uint32_t)((it & 3) * 8192), lane, wid * 16, acc);
        float *zcol = Zp + it * 64;
#pragma unroll
        for (int nt = 0; nt < 8; ++nt) {
            float e0 = fast_exp(acc[nt][0] * 0.125f);
            float e1 = fast_exp(acc[nt][1] * 0.125f);
            float e2 = fast_exp(acc[nt][2] * 0.125f);
            float e3 = fast_exp(acc[nt][3] * 0.125f);
            float c0 = e0 + e2, c1 = e1 + e3;
#pragma unroll
            for (int o = 4; o < 32; o <<= 1) {
                c0 += __shfl_xor_sync(0xffffffffu, c0, o);
                c1 += __shfl_xor_sync(0xffffffffu, c1, o);
            }
            if (lane < 4) {
                atomicAdd(zcol + nt * 8 + lane * 2, c0);
                atomicAdd(zcol + nt * 8 + lane * 2 + 1, c1);
            }
        }
        __syncthreads();
    }
}

// ---------------- kernel 3: V' = (V * 1/Z) transposed fp16 ----------------
__global__ void __launch_bounds__(256) vsplit_mm() {
    __shared__ float ts[64][65];
    __shared__ float rz[64];
    const int tid = threadIdx.x;
    const int s0 = blockIdx.x * 64, bh = blockIdx.y;
    const float *Vb = g_Vp + ((size_t)bh * NL + s0) * NDK;
#pragma unroll
    for (int i = 0; i < 4; ++i) {
        int idx = tid + i * 256;
        int r = idx >> 4, c4 = (idx & 15) * 4;
        float4 v = *(const float4 *)(Vb + (size_t)r * NDK + c4);
        ts[r][c4] = v.x; ts[r][c4 + 1] = v.y; ts[r][c4 + 2] = v.z; ts[r][c4 + 3] = v.w;
    }
    if (tid < 64) rz[tid] = 1.0f / g_Z[(size_t)bh * NL + s0 + tid];
    __syncthreads();
    __half *Oh = g_VT + (size_t)bh * NDK * NL + s0;
#pragma unroll
    for (int i = 0; i < 8; ++i) {
        int idx = tid + i * 256;
        int v = idx >> 5, sp = (idx & 31) * 2;
        *(uint32_t *)(Oh + (size_t)v * NL + sp) = packh2(ts[sp][v] * rz[sp], ts[sp + 1][v] * rz[sp + 1]);
    }
}

// ---------------- kernel 4 (phase 2): O = exp(S)·V' fused, 4-stage ----------------
#define P2_SMEM 81920
__global__ void __launch_bounds__(256, 2) attn_mm() {
    extern __shared__ char smem[];
    uint32_t sb = s2u(smem);
    const int tid = threadIdx.x, lane = tid & 31, wid = tid >> 5;
    const int q0 = blockIdx.x * 128, bh = blockIdx.y;
    const int bb = bh >> 4, h = bh & 15;
    const __half *Kp = g_K + (size_t)bh * NL * NDK;
    const __half *Vt = g_VT + (size_t)bh * NDK * NL;
    const uint32_t QT = sb, ST = sb + 16384;
    cp_tile(QT, g_Q + ((size_t)bh * NL + q0) * NDK, 128, NDK, tid);
#pragma unroll
    for (int p = 0; p < 3; ++p) {
        uint32_t st = ST + (uint32_t)(p * 16384);
        cpa_rows<64>(st, Kp + (size_t)p * 64 * NDK, NDK, tid);
        cpa_rows<64>(st + 8192, Vt + (size_t)p * 64, NL, tid);
        CPA_COMMIT();
    }

    float oacc[8][4];
#pragma unroll
    for (int vt = 0; vt < 8; ++vt)
#pragma unroll
        for (int i = 0; i < 4; ++i) oacc[vt][i] = 0.f;

    for (int it = 0; it < 32; ++it) {
        if (it + 3 < 32) {
            uint32_t st = ST + (uint32_t)(((it + 3) & 3) * 16384);
            cpa_rows<64>(st, Kp + (size_t)(it + 3) * 64 * NDK, NDK, tid);
            cpa_rows<64>(st + 8192, Vt + (size_t)(it + 3) * 64, NL, tid);
        }
        CPA_COMMIT();
        CPA_WAIT3();
        __syncthreads();
        const uint32_t SS = ST + (uint32_t)((it & 3) * 16384);
        float acc[8][4];
#pragma unroll
        for (int nt = 0; nt < 8; ++nt)
#pragma unroll
            for (int i = 0; i < 4; ++i) acc[nt][i] = 0.f;
        mma1h_64(QT, SS, lane, wid * 16, acc);
#pragma unroll
        for (int kc2 = 0; kc2 < 4; ++kc2) {
            const int a = 2 * kc2, b = a + 1;
            uint32_t pa[4];
            pa[0] = packh2(fast_exp(acc[a][0] * 0.125f), fast_exp(acc[a][1] * 0.125f));
            pa[1] = packh2(fast_exp(acc[a][2] * 0.125f), fast_exp(acc[a][3] * 0.125f));
            pa[2] = packh2(fast_exp(acc[b][0] * 0.125f), fast_exp(acc[b][1] * 0.125f));
            pa[3] = packh2(fast_exp(acc[b][2] * 0.125f), fast_exp(acc[b][3] * 0.125f));
            uint32_t v0[8], v1[8];
            ldB64(SS + 8192, lane, kc2, v0, v1);
#pragma unroll
            for (int vt = 0; vt < 8; ++vt) mma16816(oacc[vt], pa, v0[vt], v1[vt]);
        }
        __syncthreads();
    }
    const int r = lane >> 2, c2 = (lane & 3) * 2;
    const size_t row0 = ((size_t)bb * NL + q0 + wid * 16 + r) * NDM + h * NDK;
    const size_t row1 = row0 + 8 * NDM;
#pragma unroll
    for (int vt = 0; vt < 8; ++vt) {
        int col = vt * 8 + c2;
        *(uint32_t *)(g_O + row0 + col) = packh2(oacc[vt][0], oacc[vt][1]);
        *(uint32_t *)(g_O + row1 + col) = packh2(oacc[vt][2], oacc[vt][3]);
    }
}

// ---------------- kernel 5: out = cat_V @ Wo + bo (128x128) ----------------
__global__ void __launch_bounds__(256, 2) out_mm(const float *__restrict__ bo, float *__restrict__ out) {
    extern __shared__ char smem[];
    uint32_t sb = s2u(smem);
    const int tid = threadIdx.x, lane = tid & 31, wid = tid >> 5;
    const int wm = wid >> 1, wn = wid & 1;
    const int row0 = blockIdx.x * 128;
    const int n0 = blockIdx.y * 128;
    const __half *Ap = g_O + (size_t)row0 * NDM;
    const __half *Bp = g_WoT + (size_t)n0 * NDM;

    cpa_rows<128>(sb + OFF_A, Ap, NDM, tid);
    cpa_rows<128>(sb + OFF_B, Bp, NDM, tid);
    CPA_COMMIT();

    float acc[2][8][4];
    ACC_ZERO28(acc);
    for (int it = 0; it < 16; ++it) {
        if (it < 15) {
            uint32_t st = sb + (uint32_t)(((it + 1) & 1) * GBUF);
            cpa_rows<128>(st + OFF_A, Ap + (it + 1) * 64, NDM, tid);
            cpa_rows<128>(st + OFF_B, Bp + (it + 1) * 64, NDM, tid);
            CPA_COMMIT();
            CPA_WAIT1();
        } else {
            CPA_WAIT0();
        }
        __syncthreads();
        mma_tile_s(sb + (uint32_t)((it & 1) * GBUF), lane, wm, wn, acc);
        __syncthreads();
    }
    const int trow = lane >> 2, tc = (lane & 3) * 2;
#pragma unroll
    for (int mt = 0; mt < 2; ++mt)
#pragma unroll
        for (int nt = 0; nt < 8; ++nt) {
            int col = n0 + wn * 64 + nt * 8 + tc;
            float2 b2 = *(const float2 *)(bo + col);
#pragma unroll
            for (int hh = 0; hh < 2; ++hh) {
                int row = row0 + wm * 32 + mt * 16 + trow + hh * 8;
                *(float2 *)(out + (size_t)row * NDM + col) =
                    make_float2(acc[mt][nt][2 * hh] + b2.x, acc[mt][nt][2 * hh + 1] + b2.y);
            }
        }
}

// ---------------- launch ----------------
extern "C" void kernel_launch(void *const *d_in, const int *in_sizes, int n_in,
                              void *d_out, int out_size) {
    const float *Q = (const float *)d_in[0];
    const float *K = (const float *)d_in[1];
    const float *V = (const float *)d_in[2];
    const float *Wq = (const float *)d_in[3];
    const float *bq = (const float *)d_in[4];
    const float *Wk = (const float *)d_in[5];
    const float *bk = (const float *)d_in[6];
    const float *Wv = (const float *)d_in[7];
    const float *bv = (const float *)d_in[8];
    const float *Wo = (const float *)d_in[9];
    const float *bo = (const float *)d_in[10];
    float *out = (float *)d_out;

    cudaFuncSetAttribute(proj_mm, cudaFuncAttributeMaxDynamicSharedMemorySize, PJ_SMEM);
    cudaFuncSetAttribute(phase1_mm, cudaFuncAttributeMaxDynamicSharedMemorySize, P1_SMEM);
    cudaFuncSetAttribute(attn_mm, cudaFuncAttributeMaxDynamicSharedMemorySize, P2_SMEM);
    cudaFuncSetAttribute(out_mm, cudaFuncAttributeMaxDynamicSharedMemorySize, PJ_SMEM);

    tofp16<<<dim3(NM * NDM / (256 * 8), 3), 256>>>(Q, K, V);
    prep_wqkv<<<dim3(16, NH, 3), 256>>>(Wq, Wk, Wv);
    prep_wo<<<dim3(16, 16), 256>>>(Wo);
    proj_mm<<<dim3(NH / 2, NM / 128, 3), 256, PJ_SMEM>>>(bq, bk, bv);  // 4th launch -> profiled
    zeroZ<<<64, 1024>>>();
    phase1_mm<<<dim3(NL / 128, NBH), 256, P1_SMEM>>>();
    vsplit_mm<<<dim3(NL / 64, NBH), 256>>>();
    attn_mm<<<dim3(NL / 128, NBH), 256, P2_SMEM>>>();
    out_mm<<<dim3(NM / 128, NDM / 128), 256, PJ_SMEM>>>(bo, out);
}